// round 2
// baseline (speedup 1.0000x reference)
#include <cuda_runtime.h>
#include <math.h>

#define SP    512
#define DIN   1536
#define NH    32
#define HD    128
#define HDTOT 4096

// ---------------- scratch (device globals; no allocations) ----------------
__device__ float g_xnorm[SP * DIN];
__device__ float g_xgelu[SP * DIN];
__device__ float g_q[SP * HDTOT];
__device__ float g_k[SP * HDTOT];
__device__ float g_yq[SP * HD];
__device__ float g_yk[SP * HD];
// suffix tables: [j 0..32][q 0..511][h 0..31][2] = {SA (incl b_pos term), SB}
__device__ float g_TQ[33 * SP * NH * 2];
__device__ float g_TK[33 * SP * NH * 2];
__device__ int   g_f0[SP];

// ---------------- K1: pool + rmsnorm + gelu ----------------
__global__ void k_pool(const float* __restrict__ x, const float* __restrict__ w_rms,
                       float* __restrict__ xnorm, float* __restrict__ xgelu) {
    int sp = blockIdx.x;
    const float* xb = x + (size_t)sp * 16 * DIN;
    __shared__ float xp[DIN];
    __shared__ float red[256];
    int t = threadIdx.x;
    float ssq = 0.f;
    for (int c = t; c < DIN; c += 256) {
        float s = 0.f;
        #pragma unroll
        for (int r = 0; r < 16; r++) s += xb[r * DIN + c];
        s *= (1.f / 16.f);
        xp[c] = s;
        ssq += s * s;
    }
    red[t] = ssq;
    __syncthreads();
    for (int o = 128; o > 0; o >>= 1) {
        if (t < o) red[t] += red[t + o];
        __syncthreads();
    }
    float scale = rsqrtf(red[0] / (float)DIN + 1e-6f);
    for (int c = t; c < DIN; c += 256) {
        float v = xp[c] * scale * w_rms[c];
        xnorm[sp * DIN + c] = v;
        xgelu[sp * DIN + c] = v * normcdff(v);  // exact gelu: x * Phi(x)
    }
}

// ---------------- K2: fp32 SGEMM  C[M,N] = A[M,K] @ B[K,N] ----------------
// BM=64 BN=64 BK=16, 256 threads, 4x4 per thread. M%64==0, N%64==0, K%16==0.
__global__ void __launch_bounds__(256) k_sgemm(const float* __restrict__ A,
                                               const float* __restrict__ B,
                                               float* __restrict__ C,
                                               int M, int N, int K) {
    __shared__ float As[16][64];
    __shared__ float Bs[16][68];
    int t = threadIdx.x;
    int m0 = blockIdx.y * 64, n0 = blockIdx.x * 64;
    int arow = t >> 2, acol = (t & 3) * 4;
    int brow = t >> 4, bcol = (t & 15) * 4;
    int tm = (t >> 4) * 4, tn = (t & 15) * 4;
    float acc[4][4];
    #pragma unroll
    for (int i = 0; i < 4; i++)
        #pragma unroll
        for (int j = 0; j < 4; j++) acc[i][j] = 0.f;

    for (int k0 = 0; k0 < K; k0 += 16) {
        float4 av = *(const float4*)&A[(size_t)(m0 + arow) * K + k0 + acol];
        As[acol + 0][arow] = av.x;
        As[acol + 1][arow] = av.y;
        As[acol + 2][arow] = av.z;
        As[acol + 3][arow] = av.w;
        float4 bv = *(const float4*)&B[(size_t)(k0 + brow) * N + n0 + bcol];
        *(float4*)&Bs[brow][bcol] = bv;
        __syncthreads();
        #pragma unroll
        for (int k = 0; k < 16; k++) {
            float a[4], b[4];
            *(float4*)a = *(const float4*)&As[k][tm];
            *(float4*)b = *(const float4*)&Bs[k][tn];
            #pragma unroll
            for (int i = 0; i < 4; i++)
                #pragma unroll
                for (int j = 0; j < 4; j++) acc[i][j] = fmaf(a[i], b[j], acc[i][j]);
        }
        __syncthreads();
    }
    #pragma unroll
    for (int i = 0; i < 4; i++) {
        float4 v = make_float4(acc[i][0], acc[i][1], acc[i][2], acc[i][3]);
        *(float4*)&C[(size_t)(m0 + tm + i) * N + n0 + tn] = v;
    }
}

// ---------------- K3: f0 table (count of center_widths <= d) ----------------
__global__ void k_f0(int* __restrict__ f0) {
    int d = threadIdx.x;
    if (d < SP) {
        const float log_step = (float)(log(481.0) / 32.0);  // log(512-32+1)/32
        int cnt = 0;
        #pragma unroll
        for (int f = 0; f < 32; f++) {
            float cw = (float)f + expf((float)f * log_step);
            if (cw <= (float)d) cnt++;
        }
        f0[d] = cnt;
    }
}

// ---------------- K4: suffix tables ----------------
// For each (h, q): M[f] = sum_c (qk[q,h,c]+rbias[h,c]) * W_pos[f, h*128+c], f<64
//                  Cb   = sum_c (..) * b_pos[h*128+c]
// SA[j] = Cb + sum_{f=j..31} M[f];  SB[j] = sum_{f=j..31} M[32+f]
// stored at T[((j*512+q)*32+h)*2 + {0,1}]
__global__ void __launch_bounds__(256) k_suffix(const float* __restrict__ qk,
                                                const float* __restrict__ rbias,
                                                const float* __restrict__ W_pos,
                                                const float* __restrict__ b_pos,
                                                float* __restrict__ T) {
    extern __shared__ float sm[];
    float* ws = sm;              // 65 rows (64 W_pos + 1 b_pos) x 132
    float* qs = ws + 65 * 132;   // 32 x 132
    float* Ms = qs + 32 * 132;   // 32 x 65
    int h = blockIdx.y;
    int q0 = blockIdx.x * 32;
    int t = threadIdx.x;

    for (int i = t; i < 65 * 128; i += 256) {
        int f = i >> 7, c = i & 127;
        float v = (f < 64) ? W_pos[f * HDTOT + h * HD + c] : b_pos[h * HD + c];
        ws[f * 132 + c] = v;
    }
    for (int i = t; i < 32 * 128; i += 256) {
        int r = i >> 7, c = i & 127;
        qs[r * 132 + c] = qk[(size_t)(q0 + r) * HDTOT + h * HD + c] + rbias[h * HD + c];
    }
    __syncthreads();
    for (int i = t; i < 32 * 65; i += 256) {
        int r = i / 65, f = i % 65;
        const float4* qr = (const float4*)&qs[r * 132];
        const float4* wr = (const float4*)&ws[f * 132];
        float acc = 0.f;
        #pragma unroll
        for (int c4 = 0; c4 < 32; c4++) {
            float4 a = qr[c4], b = wr[c4];
            acc += a.x * b.x + a.y * b.y + a.z * b.z + a.w * b.w;
        }
        Ms[r * 65 + f] = acc;
    }
    __syncthreads();
    for (int i = t; i < 32 * 33; i += 256) {
        int r = i / 33, j = i % 33;
        float sa = Ms[r * 65 + 64];  // b_pos contribution
        float sb = 0.f;
        for (int f = j; f < 32; f++) {
            sa += Ms[r * 65 + f];
            sb += Ms[r * 65 + 32 + f];
        }
        int q = q0 + r;
        int base = ((j * SP + q) * NH + h) * 2;
        T[base] = sa;
        T[base + 1] = sb;
    }
}

// ---------------- K5: fused pair kernel ----------------
// Per block: 32x32 (q,k) tile.
// pass1: A[q,k,h] = dot_c(qbuf, kbuf) per head, 2x2 reg blocking.
// rel:   A += 0.5*(term_q + term_k) via suffix-table gathers (f0 trick).
// pass2: out[q,k,d] = sum_h A*Wp[h,d] + b_pair[d] + yq[q,d] + yk[k,d]
#define AS_STRIDE 36   // pad 32->36 so each pair row is 144B (16B aligned)
__global__ void __launch_bounds__(256) k_pair(const float* __restrict__ qb,
                                              const float* __restrict__ kb,
                                              const float* __restrict__ TQ,
                                              const float* __restrict__ TK,
                                              const int* __restrict__ f0tab,
                                              const float* __restrict__ Wp,
                                              const float* __restrict__ bp,
                                              const float* __restrict__ yq,
                                              const float* __restrict__ yk,
                                              float* __restrict__ out) {
    extern __shared__ float sm[];
    float* As = sm;                       // 32*32*AS_STRIDE
    float* qs = As + 32 * 32 * AS_STRIDE; // 32*132
    float* ks = qs + 32 * 132;            // 32*132
    int t = threadIdx.x;
    int q0 = blockIdx.y * 32, k0 = blockIdx.x * 32;
    int ty = t >> 4, tx = t & 15;

    for (int h = 0; h < NH; h++) {
        __syncthreads();
        for (int i = t; i < 1024; i += 256) {
            int r = i >> 5, c4 = i & 31;
            *(float4*)&qs[r * 132 + c4 * 4] =
                *(const float4*)&qb[(size_t)(q0 + r) * HDTOT + h * HD + c4 * 4];
            *(float4*)&ks[r * 132 + c4 * 4] =
                *(const float4*)&kb[(size_t)(k0 + r) * HDTOT + h * HD + c4 * 4];
        }
        __syncthreads();
        float a00 = 0.f, a01 = 0.f, a10 = 0.f, a11 = 0.f;
        const float4* q0p = (const float4*)&qs[ty * 132];
        const float4* q1p = (const float4*)&qs[(ty + 16) * 132];
        const float4* k0p = (const float4*)&ks[tx * 132];
        const float4* k1p = (const float4*)&ks[(tx + 16) * 132];
        #pragma unroll
        for (int c4 = 0; c4 < 32; c4++) {
            float4 rq0 = q0p[c4], rq1 = q1p[c4], rk0 = k0p[c4], rk1 = k1p[c4];
            a00 += rq0.x * rk0.x + rq0.y * rk0.y + rq0.z * rk0.z + rq0.w * rk0.w;
            a01 += rq0.x * rk1.x + rq0.y * rk1.y + rq0.z * rk1.z + rq0.w * rk1.w;
            a10 += rq1.x * rk0.x + rq1.y * rk0.y + rq1.z * rk0.z + rq1.w * rk0.w;
            a11 += rq1.x * rk1.x + rq1.y * rk1.y + rq1.z * rk1.z + rq1.w * rk1.w;
        }
        As[(ty * 32 + tx) * AS_STRIDE + h] = a00;
        As[(ty * 32 + tx + 16) * AS_STRIDE + h] = a01;
        As[((ty + 16) * 32 + tx) * AS_STRIDE + h] = a10;
        As[((ty + 16) * 32 + tx + 16) * AS_STRIDE + h] = a11;
    }

    // relative-position terms (suffix-table gathers), each thread its own pairs
    #pragma unroll
    for (int p = 0; p < 4; p++) {
        int qi = (p >> 1) ? (ty + 16) : ty;
        int ki = (p & 1) ? (tx + 16) : tx;
        int q = q0 + qi, k = k0 + ki;
        int delta = k - q;
        int dd = delta >= 0 ? delta : -delta;
        float sgn = delta > 0 ? 1.f : (delta < 0 ? -1.f : 0.f);
        int j = f0tab[dd];
        const float4* tq4 = (const float4*)&TQ[(size_t)((j * SP + q) * NH) * 2];
        const float4* tk4 = (const float4*)&TK[(size_t)((j * SP + k) * NH) * 2];
        float* arow = &As[(qi * 32 + ki) * AS_STRIDE];
        #pragma unroll
        for (int h2 = 0; h2 < 16; h2++) {
            float4 a = tq4[h2], b = tk4[h2];
            arow[2 * h2]     += 0.5f * ((a.x + sgn * a.y) + (b.x - sgn * b.y));
            arow[2 * h2 + 1] += 0.5f * ((a.z + sgn * a.w) + (b.z - sgn * b.w));
        }
    }
    __syncthreads();

    // pass2: epilogue GEMM, W_pair column resident in registers
    int d = t & 127;
    int g = t >> 7;  // 0/1 -> two pairs per iteration
    float wcol[32];
    #pragma unroll
    for (int h = 0; h < 32; h++) wcol[h] = Wp[h * HD + d];
    float bpd = bp[d];
    for (int pp = 0; pp < 512; pp++) {
        int pair = pp * 2 + g;
        int qi = pair >> 5, ki = pair & 31;
        const float* arow = &As[pair * AS_STRIDE];
        float acc = bpd + yq[(q0 + qi) * HD + d] + yk[(k0 + ki) * HD + d];
        #pragma unroll
        for (int h4 = 0; h4 < 8; h4++) {
            float4 av = *(const float4*)&arow[h4 * 4];
            acc += av.x * wcol[h4 * 4] + av.y * wcol[h4 * 4 + 1] +
                   av.z * wcol[h4 * 4 + 2] + av.w * wcol[h4 * 4 + 3];
        }
        out[(size_t)((q0 + qi) * SP + (k0 + ki)) * HD + d] = acc;
    }
}

// ---------------- launcher ----------------
#define SUF_SMEM  ((65 * 132 + 32 * 132 + 32 * 65) * 4)
#define PAIR_SMEM ((32 * 32 * AS_STRIDE + 2 * 32 * 132) * 4)

extern "C" void kernel_launch(void* const* d_in, const int* in_sizes, int n_in,
                              void* d_out, int out_size) {
    const float* x      = (const float*)d_in[0];
    const float* w_rms  = (const float*)d_in[1];
    const float* W_q    = (const float*)d_in[2];
    const float* W_k    = (const float*)d_in[3];
    const float* W_pos  = (const float*)d_in[4];
    const float* b_pos  = (const float*)d_in[5];
    const float* qrb    = (const float*)d_in[6];
    const float* krb    = (const float*)d_in[7];
    const float* W_yq   = (const float*)d_in[8];
    const float* W_yk   = (const float*)d_in[9];
    const float* W_pair = (const float*)d_in[10];
    const float* b_pair = (const float*)d_in[11];
    float* out = (float*)d_out;

    float *xn, *xg, *qb, *kb, *yq, *yk, *TQ, *TK;
    int* f0;
    cudaGetSymbolAddress((void**)&xn, g_xnorm);
    cudaGetSymbolAddress((void**)&xg, g_xgelu);
    cudaGetSymbolAddress((void**)&qb, g_q);
    cudaGetSymbolAddress((void**)&kb, g_k);
    cudaGetSymbolAddress((void**)&yq, g_yq);
    cudaGetSymbolAddress((void**)&yk, g_yk);
    cudaGetSymbolAddress((void**)&TQ, g_TQ);
    cudaGetSymbolAddress((void**)&TK, g_TK);
    cudaGetSymbolAddress((void**)&f0, g_f0);

    cudaFuncSetAttribute(k_suffix, cudaFuncAttributeMaxDynamicSharedMemorySize, SUF_SMEM);
    cudaFuncSetAttribute(k_pair, cudaFuncAttributeMaxDynamicSharedMemorySize, PAIR_SMEM);

    k_pool<<<SP, 256>>>(x, w_rms, xn, xg);
    k_f0<<<1, 512>>>(f0);

    dim3 gqk(HDTOT / 64, SP / 64);
    k_sgemm<<<gqk, 256>>>(xn, W_q, qb, SP, HDTOT, DIN);
    k_sgemm<<<gqk, 256>>>(xn, W_k, kb, SP, HDTOT, DIN);
    dim3 gy(HD / 64, SP / 64);
    k_sgemm<<<gy, 256>>>(xg, W_yq, yq, SP, HD, DIN);
    k_sgemm<<<gy, 256>>>(xg, W_yk, yk, SP, HD, DIN);

    dim3 gs(SP / 32, NH);
    k_suffix<<<gs, 256, SUF_SMEM>>>(qb, qrb, W_pos, b_pos, TQ);
    k_suffix<<<gs, 256, SUF_SMEM>>>(kb, krb, W_pos, b_pos, TK);

    dim3 gp(SP / 32, SP / 32);
    k_pair<<<gp, 256, PAIR_SMEM>>>(qb, kb, TQ, TK, f0, W_pair, b_pair, yq, yk, out);
}

// round 4
// speedup vs baseline: 1.8484x; 1.8484x over previous
#include <cuda_runtime.h>
#include <cuda_bf16.h>
#include <math.h>
#include <stdint.h>

#define SP    512
#define DIN   1536
#define NH    32
#define HD    128
#define HDTOT 4096
#define K3    4608   // 3*DIN
#define KH    384    // 3*HD

// ---------------- scratch ----------------
__device__ float g_xnorm[SP*DIN];
__device__ float g_xgelu[SP*DIN];
__device__ __nv_bfloat16 g_Xn[SP*K3];       // x_norm split [hi,hi,lo]
__device__ __nv_bfloat16 g_Xg[SP*K3];       // x_gelu split [hi,hi,lo]
__device__ __nv_bfloat16 g_Ww[(size_t)2*HDTOT*K3]; // Wq|Wk transposed, split [hi,lo,hi]
__device__ __nv_bfloat16 g_Wy[2*HD*K3];     // Wyq|Wyk transposed, split [hi,lo,hi]
__device__ float g_q[SP*HDTOT];
__device__ float g_k[SP*HDTOT];
__device__ float g_yq[SP*HD];
__device__ float g_yk[SP*HD];
__device__ __nv_bfloat16 g_Qs[(size_t)NH*SP*KH];  // [h][s][384] split [hi,lo,hi]
__device__ __nv_bfloat16 g_Ks[(size_t)NH*SP*KH];  // [h][s][384] split [hi,hi,lo]
__device__ float g_S[(size_t)NH*SP*SP];     // scores [h][q][k]
__device__ float g_TQ[33*SP*NH*2];
__device__ float g_TK[33*SP*NH*2];
__device__ float g_RQ[33*SP*HD*2];
__device__ float g_RK[33*SP*HD*2];
__device__ int   g_f0[SP];

// ---------------- helpers ----------------
__device__ __forceinline__ uint32_t smem_u32(const void* p) {
    uint32_t a;
    asm("{ .reg .u64 t; cvta.to.shared.u64 t, %1; cvt.u32.u64 %0, t; }" : "=r"(a) : "l"(p));
    return a;
}
__device__ __forceinline__ void cp16(uint32_t dst, const void* src) {
    asm volatile("cp.async.cg.shared.global [%0], [%1], 16;" :: "r"(dst), "l"(src));
}
#define CP_COMMIT() asm volatile("cp.async.commit_group;" ::: "memory")
#define CP_WAIT2()  asm volatile("cp.async.wait_group 2;" ::: "memory")

__device__ __forceinline__ void ldm_x4(uint32_t* r, uint32_t addr) {
    asm volatile("ldmatrix.sync.aligned.m8n8.x4.shared.b16 {%0,%1,%2,%3}, [%4];"
                 : "=r"(r[0]), "=r"(r[1]), "=r"(r[2]), "=r"(r[3]) : "r"(addr));
}
__device__ __forceinline__ void mma16816(float* c, const uint32_t* a, uint32_t b0, uint32_t b1) {
    asm volatile("mma.sync.aligned.m16n8k16.row.col.f32.bf16.bf16.f32 "
                 "{%0,%1,%2,%3}, {%4,%5,%6,%7}, {%8,%9}, {%0,%1,%2,%3};"
                 : "+f"(c[0]), "+f"(c[1]), "+f"(c[2]), "+f"(c[3])
                 : "r"(a[0]), "r"(a[1]), "r"(a[2]), "r"(a[3]), "r"(b0), "r"(b1));
}
__device__ __forceinline__ void split2(float v, __nv_bfloat16& hi, __nv_bfloat16& lo) {
    hi = __float2bfloat16(v);
    lo = __float2bfloat16(v - __bfloat162float(hi));
}

// ---------------- K1: pool + rmsnorm + gelu ----------------
__global__ void k_pool(const float* __restrict__ x, const float* __restrict__ w_rms,
                       float* __restrict__ xnorm, float* __restrict__ xgelu) {
    int sp = blockIdx.x;
    const float* xb = x + (size_t)sp * 16 * DIN;
    __shared__ float xp[DIN];
    __shared__ float red[256];
    int t = threadIdx.x;
    float ssq = 0.f;
    for (int c = t; c < DIN; c += 256) {
        float s = 0.f;
        #pragma unroll
        for (int r = 0; r < 16; r++) s += xb[r * DIN + c];
        s *= (1.f / 16.f);
        xp[c] = s;
        ssq += s * s;
    }
    red[t] = ssq;
    __syncthreads();
    for (int o = 128; o > 0; o >>= 1) {
        if (t < o) red[t] += red[t + o];
        __syncthreads();
    }
    float scale = rsqrtf(red[0] / (float)DIN + 1e-6f);
    for (int c = t; c < DIN; c += 256) {
        float v = xp[c] * scale * w_rms[c];
        xnorm[sp * DIN + c] = v;
        xgelu[sp * DIN + c] = v * normcdff(v);
    }
}

// ---------------- K2: f0 table ----------------
__global__ void k_f0(int* __restrict__ f0) {
    int d = threadIdx.x;
    if (d < SP) {
        const float log_step = (float)(log(481.0) / 32.0);
        int cnt = 0;
        #pragma unroll
        for (int f = 0; f < 32; f++) {
            float cw = (float)f + expf((float)f * log_step);
            if (cw <= (float)d) cnt++;
        }
        f0[d] = cnt;
    }
}

// ---------------- K3: split activations [hi,hi,lo] ----------------
__global__ void k_splitx(const float* __restrict__ xn, const float* __restrict__ xg,
                         __nv_bfloat16* __restrict__ Xn, __nv_bfloat16* __restrict__ Xg) {
    int idx = blockIdx.x * 256 + threadIdx.x;
    int s = idx / DIN, c = idx % DIN;
    size_t b = (size_t)s * K3;
    __nv_bfloat16 hi, lo;
    split2(xn[idx], hi, lo);
    Xn[b + c] = hi; Xn[b + DIN + c] = hi; Xn[b + 2 * DIN + c] = lo;
    split2(xg[idx], hi, lo);
    Xg[b + c] = hi; Xg[b + DIN + c] = hi; Xg[b + 2 * DIN + c] = lo;
}

// ---------------- K4: transpose + split weights [hi,lo,hi] ----------------
__global__ void k_wsplit(const float* __restrict__ srcA, const float* __restrict__ srcB,
                         int Nsrc, __nv_bfloat16* __restrict__ dst) {
    __shared__ float tile[32][33];
    int t = threadIdx.x;
    int n0 = blockIdx.x * 32, k0 = blockIdx.y * 32;
    const float* src = (n0 < Nsrc) ? srcA : srcB;
    int nb = (n0 < Nsrc) ? n0 : (n0 - Nsrc);
    #pragma unroll
    for (int i = 0; i < 4; i++) {
        int r = (t >> 5) + i * 8, c = t & 31;
        tile[r][c] = src[(size_t)(k0 + r) * Nsrc + nb + c];
    }
    __syncthreads();
    #pragma unroll
    for (int i = 0; i < 4; i++) {
        int rn = (t >> 5) + i * 8;
        int kk = k0 + (t & 31);
        float v = tile[t & 31][rn];
        __nv_bfloat16 hi, lo;
        split2(v, hi, lo);
        size_t row = (size_t)(n0 + rn) * K3;
        dst[row + kk] = hi;
        dst[row + DIN + kk] = lo;
        dst[row + 2 * DIN + kk] = hi;
    }
}

// ---------------- K5: bf16 mma.sync GEMM (NT: A[m][k] . B[n][k]) ----------------
// CTA 128x128, 8 warps (2m x 4n), warp 64x32, BK=32, 3-stage cp.async.
// mode 0: q|k projection (+ bf16 split side-outputs)
// mode 1: y projection;  mode 2: scores batched over z
#define TILE_BYTES (128 * 80)            // 128 rows x 40 bf16 (pad 8)
#define STAGE_BYTES (2 * TILE_BYTES)
#define MMA_SMEM (3 * STAGE_BYTES)       // 61440
__global__ void __launch_bounds__(256) k_mma(
    const __nv_bfloat16* __restrict__ A, const __nv_bfloat16* __restrict__ B,
    int sA, int sB, long batA, long batB, int niter, int mode,
    float* __restrict__ o0, float* __restrict__ o1,
    __nv_bfloat16* __restrict__ b0, __nv_bfloat16* __restrict__ b1)
{
    extern __shared__ char sm[];
    uint32_t smb = smem_u32(sm);
    int t = threadIdx.x, w = t >> 5, lane = t & 31;
    int m0 = blockIdx.x * 128, n0 = blockIdx.y * 128, z = blockIdx.z;
    int wm = w >> 2, wn = w & 3;

    const __nv_bfloat16* Ab = A + batA * z + (size_t)m0 * sA;
    const __nv_bfloat16* Bb = B + batB * z + (size_t)n0 * sB;

    float c[4][4][4];
    #pragma unroll
    for (int i = 0; i < 4; i++)
        #pragma unroll
        for (int j = 0; j < 4; j++)
            #pragma unroll
            for (int e = 0; e < 4; e++) c[i][j][e] = 0.f;

    uint32_t aoff[4], boff[2];
    {
        int lr = lane & 15, lc = lane >> 4;
        #pragma unroll
        for (int mi = 0; mi < 4; mi++) aoff[mi] = (wm * 64 + mi * 16 + lr) * 80 + lc * 16;
        #pragma unroll
        for (int nj = 0; nj < 2; nj++) boff[nj] = TILE_BYTES + (wn * 32 + nj * 16 + lr) * 80 + lc * 16;
    }
    int lrow = t >> 2, lc16 = (t & 3) * 16;       // load: row, byte-col within 64B
    int lcol_el = (t & 3) * 8;

    // prologue: stages 0,1
    #pragma unroll
    for (int s = 0; s < 2; s++) {
        if (s < niter) {
            uint32_t db = smb + s * STAGE_BYTES;
            #pragma unroll
            for (int i = 0; i < 2; i++) {
                int row = lrow + i * 64;
                uint32_t d = db + row * 80 + lc16;
                cp16(d, Ab + (size_t)row * sA + s * 32 + lcol_el);
                cp16(d + TILE_BYTES, Bb + (size_t)row * sB + s * 32 + lcol_el);
            }
        }
        CP_COMMIT();
    }

    for (int ck = 0; ck < niter; ck++) {
        int pf = ck + 2;
        if (pf < niter) {
            uint32_t db = smb + (pf % 3) * STAGE_BYTES;
            #pragma unroll
            for (int i = 0; i < 2; i++) {
                int row = lrow + i * 64;
                uint32_t d = db + row * 80 + lc16;
                cp16(d, Ab + (size_t)row * sA + pf * 32 + lcol_el);
                cp16(d + TILE_BYTES, Bb + (size_t)row * sB + pf * 32 + lcol_el);
            }
        }
        CP_COMMIT();
        CP_WAIT2();
        __syncthreads();
        uint32_t sa = smb + (ck % 3) * STAGE_BYTES;
        #pragma unroll
        for (int kk = 0; kk < 2; kk++) {
            uint32_t a[4][4], b[2][4];
            #pragma unroll
            for (int mi = 0; mi < 4; mi++) ldm_x4(a[mi], sa + aoff[mi] + kk * 32);
            #pragma unroll
            for (int nj = 0; nj < 2; nj++) ldm_x4(b[nj], sa + boff[nj] + kk * 32);
            #pragma unroll
            for (int mi = 0; mi < 4; mi++)
                #pragma unroll
                for (int ni = 0; ni < 4; ni++)
                    mma16816(c[mi][ni], a[mi], b[ni >> 1][ni & 1], b[ni >> 1][(ni & 1) + 2]);
        }
        __syncthreads();
    }

    // epilogue
    int r0 = lane >> 2, c0 = (lane & 3) * 2;
    #pragma unroll
    for (int mi = 0; mi < 4; mi++) {
        #pragma unroll
        for (int ni = 0; ni < 4; ni++) {
            #pragma unroll
            for (int half = 0; half < 2; half++) {
                int row = m0 + wm * 64 + mi * 16 + r0 + half * 8;
                int col = n0 + wn * 32 + ni * 8 + c0;
                float v0 = c[mi][ni][half * 2], v1 = c[mi][ni][half * 2 + 1];
                if (mode == 0) {
                    bool isQ = col < HDTOT;
                    int nn = isQ ? col : col - HDTOT;
                    float* o = isQ ? o0 : o1;
                    float2 fv = make_float2(v0, v1);
                    *(float2*)&o[(size_t)row * HDTOT + nn] = fv;
                    __nv_bfloat16* bs = isQ ? b0 : b1;
                    #pragma unroll
                    for (int e = 0; e < 2; e++) {
                        int ne = nn + e;
                        int h = ne >> 7, cc = ne & 127;
                        __nv_bfloat16* p = bs + ((size_t)h * SP + row) * KH + cc;
                        __nv_bfloat16 hi, lo;
                        split2(e ? v1 : v0, hi, lo);
                        if (isQ) { p[0] = hi; p[128] = lo; p[256] = hi; }
                        else     { p[0] = hi; p[128] = hi; p[256] = lo; }
                    }
                } else if (mode == 1) {
                    bool isQ = col < HD;
                    int nn = isQ ? col : col - HD;
                    float* o = isQ ? o0 : o1;
                    float2 fv = make_float2(v0, v1);
                    *(float2*)&o[(size_t)row * HD + nn] = fv;
                } else {
                    float2 fv = make_float2(v0, v1);
                    *(float2*)&o0[((size_t)(z * SP + row)) * SP + col] = fv;
                }
            }
        }
    }
}

// ---------------- K6: suffix tables ----------------
__global__ void __launch_bounds__(256) k_suffix(const float* __restrict__ qk,
                                                const float* __restrict__ rbias,
                                                const float* __restrict__ W_pos,
                                                const float* __restrict__ b_pos,
                                                float* __restrict__ T) {
    extern __shared__ float smf[];
    float* ws = smf;
    float* qs = ws + 65 * 132;
    float* Ms = qs + 32 * 132;
    int h = blockIdx.y;
    int q0 = blockIdx.x * 32;
    int t = threadIdx.x;
    for (int i = t; i < 65 * 128; i += 256) {
        int f = i >> 7, c = i & 127;
        ws[f * 132 + c] = (f < 64) ? W_pos[f * HDTOT + h * HD + c] : b_pos[h * HD + c];
    }
    for (int i = t; i < 32 * 128; i += 256) {
        int r = i >> 7, c = i & 127;
        qs[r * 132 + c] = qk[(size_t)(q0 + r) * HDTOT + h * HD + c] + rbias[h * HD + c];
    }
    __syncthreads();
    for (int i = t; i < 32 * 65; i += 256) {
        int r = i / 65, f = i % 65;
        const float4* qr = (const float4*)&qs[r * 132];
        const float4* wr = (const float4*)&ws[f * 132];
        float acc = 0.f;
        #pragma unroll
        for (int c4 = 0; c4 < 32; c4++) {
            float4 a = qr[c4], b = wr[c4];
            acc += a.x * b.x + a.y * b.y + a.z * b.z + a.w * b.w;
        }
        Ms[r * 65 + f] = acc;
    }
    __syncthreads();
    for (int i = t; i < 32 * 33; i += 256) {
        int r = i / 33, j = i % 33;
        float sa = Ms[r * 65 + 64];
        float sb = 0.f;
        for (int f = j; f < 32; f++) { sa += Ms[r * 65 + f]; sb += Ms[r * 65 + 32 + f]; }
        int q = q0 + r;
        T[((j * SP + q) * NH + h) * 2] = sa;
        T[((j * SP + q) * NH + h) * 2 + 1] = sb;
    }
}

// ---------------- K7: fold suffix tables through W_pair ----------------
__global__ void __launch_bounds__(128) k_fold(const float* __restrict__ TQ,
                                              const float* __restrict__ TK,
                                              const float* __restrict__ Wp,
                                              float* __restrict__ RQ,
                                              float* __restrict__ RK) {
    __shared__ float tq[64], tk[64], wps[NH * HD];
    int q = blockIdx.x, j = blockIdx.y, t = threadIdx.x;
    size_t base = (size_t)(j * SP + q) * 64;
    if (t < 64) tq[t] = TQ[base + t];
    else tk[t - 64] = TK[base + t - 64];
    for (int i = t; i < NH * HD; i += 128) wps[i] = Wp[i];
    __syncthreads();
    float aa = 0.f, ab = 0.f, ba = 0.f, bb = 0.f;
    #pragma unroll
    for (int h = 0; h < NH; h++) {
        float w = wps[h * HD + t];
        aa += tq[2 * h] * w;  ab += tq[2 * h + 1] * w;
        ba += tk[2 * h] * w;  bb += tk[2 * h + 1] * w;
    }
    size_t ob = (size_t)(j * SP + q) * 256 + t * 2;
    RQ[ob] = aa; RQ[ob + 1] = ab;
    RK[ob] = ba; RK[ob + 1] = bb;
}

// ---------------- K8: final pass (FFMA) ----------------
__global__ void __launch_bounds__(256) k_pair2(const float* __restrict__ S,
                                               const float* __restrict__ RQ,
                                               const float* __restrict__ RK,
                                               const int* __restrict__ f0tab,
                                               const float* __restrict__ Wp,
                                               const float* __restrict__ bp,
                                               const float* __restrict__ yq,
                                               const float* __restrict__ yk,
                                               float* __restrict__ out) {
    __shared__ float Sh[128 * 36];
    int t = threadIdx.x;
    int q = blockIdx.x, k0 = blockIdx.y * 128;
    for (int i = t; i < 4096; i += 256) {
        int h = i >> 7, kk = i & 127;
        Sh[kk * 36 + h] = S[(((size_t)h * SP + q) << 9) + k0 + kk];
    }
    int d = t & 127, g = t >> 7;
    float wcol[NH];
    #pragma unroll
    for (int h = 0; h < NH; h++) wcol[h] = Wp[h * HD + d];
    float base0 = bp[d] + yq[q * HD + d];
    __syncthreads();
    for (int kk = g * 64; kk < g * 64 + 64; kk++) {
        int k = k0 + kk;
        int delta = k - q;
        int dd = delta >= 0 ? delta : -delta;
        float sgn = delta > 0 ? 1.f : (delta < 0 ? -1.f : 0.f);
        int j = f0tab[dd];
        float2 rq = *(const float2*)&RQ[(size_t)(j * SP + q) * 256 + d * 2];
        float2 rk = *(const float2*)&RK[(size_t)(j * SP + k) * 256 + d * 2];
        float acc = base0 + yk[k * HD + d]
                  + 0.5f * (rq.x + rk.x) + 0.5f * sgn * (rq.y - rk.y);
        const float* sr = &Sh[kk * 36];
        #pragma unroll
        for (int h4 = 0; h4 < 8; h4++) {
            float4 sv = *(const float4*)&sr[h4 * 4];
            acc += sv.x * wcol[h4 * 4] + sv.y * wcol[h4 * 4 + 1] +
                   sv.z * wcol[h4 * 4 + 2] + sv.w * wcol[h4 * 4 + 3];
        }
        out[((size_t)(q * SP + k)) * HD + d] = acc;
    }
}

// ---------------- launcher ----------------
#define SUF_SMEM ((65 * 132 + 32 * 132 + 32 * 65) * 4)

extern "C" void kernel_launch(void* const* d_in, const int* in_sizes, int n_in,
                              void* d_out, int out_size) {
    const float* x      = (const float*)d_in[0];
    const float* w_rms  = (const float*)d_in[1];
    const float* W_q    = (const float*)d_in[2];
    const float* W_k    = (const float*)d_in[3];
    const float* W_pos  = (const float*)d_in[4];
    const float* b_pos  = (const float*)d_in[5];
    const float* qrb    = (const float*)d_in[6];
    const float* krb    = (const float*)d_in[7];
    const float* W_yq   = (const float*)d_in[8];
    const float* W_yk   = (const float*)d_in[9];
    const float* W_pair = (const float*)d_in[10];
    const float* b_pair = (const float*)d_in[11];
    float* out = (float*)d_out;

    float *xn, *xg, *qb, *kb, *yq, *yk, *TQ, *TK, *RQ, *RK, *Sb;
    __nv_bfloat16 *Xn, *Xg, *Ww, *Wy, *Qs, *Ks;
    int* f0;
    cudaGetSymbolAddress((void**)&xn, g_xnorm);
    cudaGetSymbolAddress((void**)&xg, g_xgelu);
    cudaGetSymbolAddress((void**)&qb, g_q);
    cudaGetSymbolAddress((void**)&kb, g_k);
    cudaGetSymbolAddress((void**)&yq, g_yq);
    cudaGetSymbolAddress((void**)&yk, g_yk);
    cudaGetSymbolAddress((void**)&TQ, g_TQ);
    cudaGetSymbolAddress((void**)&TK, g_TK);
    cudaGetSymbolAddress((void**)&RQ, g_RQ);
    cudaGetSymbolAddress((void**)&RK, g_RK);
    cudaGetSymbolAddress((void**)&Sb, g_S);
    cudaGetSymbolAddress((void**)&Xn, g_Xn);
    cudaGetSymbolAddress((void**)&Xg, g_Xg);
    cudaGetSymbolAddress((void**)&Ww, g_Ww);
    cudaGetSymbolAddress((void**)&Wy, g_Wy);
    cudaGetSymbolAddress((void**)&Qs, g_Qs);
    cudaGetSymbolAddress((void**)&Ks, g_Ks);
    cudaGetSymbolAddress((void**)&f0, g_f0);

    cudaFuncSetAttribute(k_mma, cudaFuncAttributeMaxDynamicSharedMemorySize, MMA_SMEM);
    cudaFuncSetAttribute(k_suffix, cudaFuncAttributeMaxDynamicSharedMemorySize, SUF_SMEM);

    k_pool<<<SP, 256>>>(x, w_rms, xn, xg);
    k_f0<<<1, 512>>>(f0);
    k_splitx<<<SP * DIN / 256, 256>>>(xn, xg, Xn, Xg);
    k_wsplit<<<dim3(2 * HDTOT / 32, DIN / 32), 256>>>(W_q, W_k, HDTOT, Ww);
    k_wsplit<<<dim3(2 * HD / 32, DIN / 32), 256>>>(W_yq, W_yk, HD, Wy);

    // q|k projection: A = Xn (512 x K3), B = Ww (8192 x K3)
    k_mma<<<dim3(4, 64), 256, MMA_SMEM>>>(Xn, Ww, K3, K3, 0, 0, K3 / 32, 0, qb, kb, Qs, Ks);
    // y projection: A = Xg, B = Wy (256 x K3)
    k_mma<<<dim3(4, 2), 256, MMA_SMEM>>>(Xg, Wy, K3, K3, 0, 0, K3 / 32, 1, yq, yk, 0, 0);

    dim3 gs(SP / 32, NH);
    k_suffix<<<gs, 256, SUF_SMEM>>>(qb, qrb, W_pos, b_pos, TQ);
    k_suffix<<<gs, 256, SUF_SMEM>>>(kb, krb, W_pos, b_pos, TK);
    k_fold<<<dim3(SP, 33), 128>>>(TQ, TK, W_pair, RQ, RK);

    // scores: per-head 512x512x384
    k_mma<<<dim3(4, 4, NH), 256, MMA_SMEM>>>(Qs, Ks, KH, KH, (long)SP * KH, (long)SP * KH,
                                             KH / 32, 2, Sb, 0, 0, 0);

    k_pair2<<<dim3(SP, 4), 256>>>(Sb, RQ, RK, f0, W_pair, b_pair, yq, yk, out);
}

// round 5
// speedup vs baseline: 1.9887x; 1.0759x over previous
#include <cuda_runtime.h>
#include <cuda_bf16.h>
#include <math.h>
#include <stdint.h>

#define SP    512
#define DIN   1536
#define NH    32
#define HD    128
#define HDTOT 4096
#define K3    4608   // 3*DIN
#define KH    384    // 3*HD

// ---------------- scratch ----------------
__device__ __nv_bfloat16 g_Xn[SP*K3];       // x_norm split [hi,hi,lo]
__device__ __nv_bfloat16 g_Xg[SP*K3];       // x_gelu split [hi,hi,lo]
__device__ __nv_bfloat16 g_Ww[(size_t)2*HDTOT*K3]; // Wq|Wk transposed, split [hi,lo,hi]
__device__ __nv_bfloat16 g_Wy[2*HD*K3];     // Wyq|Wyk transposed, split [hi,lo,hi]
__device__ float g_q[SP*HDTOT];
__device__ float g_k[SP*HDTOT];
__device__ float g_yq[SP*HD];
__device__ float g_yk[SP*HD];
__device__ __nv_bfloat16 g_Qs[(size_t)NH*SP*KH];  // [h][s][384] split [hi,lo,hi]
__device__ __nv_bfloat16 g_Ks[(size_t)NH*SP*KH];  // [h][s][384] split [hi,hi,lo]
__device__ float g_S[(size_t)NH*SP*SP];     // scores [h][q][k]
__device__ float g_TQ[33*SP*NH*2];
__device__ float g_TK[33*SP*NH*2];
__device__ float g_RQ[33*SP*HD*2];
__device__ float g_RK[33*SP*HD*2];
__device__ int   g_f0[SP];

// ---------------- helpers ----------------
__device__ __forceinline__ uint32_t smem_u32(const void* p) {
    uint32_t a;
    asm("{ .reg .u64 t; cvta.to.shared.u64 t, %1; cvt.u32.u64 %0, t; }" : "=r"(a) : "l"(p));
    return a;
}
__device__ __forceinline__ void cp16(uint32_t dst, const void* src) {
    asm volatile("cp.async.cg.shared.global [%0], [%1], 16;" :: "r"(dst), "l"(src));
}
#define CP_COMMIT() asm volatile("cp.async.commit_group;" ::: "memory")
#define CP_WAIT2()  asm volatile("cp.async.wait_group 2;" ::: "memory")

__device__ __forceinline__ void ldm_x4(uint32_t* r, uint32_t addr) {
    asm volatile("ldmatrix.sync.aligned.m8n8.x4.shared.b16 {%0,%1,%2,%3}, [%4];"
                 : "=r"(r[0]), "=r"(r[1]), "=r"(r[2]), "=r"(r[3]) : "r"(addr));
}
__device__ __forceinline__ void mma16816(float* c, const uint32_t* a, uint32_t b0, uint32_t b1) {
    asm volatile("mma.sync.aligned.m16n8k16.row.col.f32.bf16.bf16.f32 "
                 "{%0,%1,%2,%3}, {%4,%5,%6,%7}, {%8,%9}, {%0,%1,%2,%3};"
                 : "+f"(c[0]), "+f"(c[1]), "+f"(c[2]), "+f"(c[3])
                 : "r"(a[0]), "r"(a[1]), "r"(a[2]), "r"(a[3]), "r"(b0), "r"(b1));
}
__device__ __forceinline__ void split2(float v, __nv_bfloat16& hi, __nv_bfloat16& lo) {
    hi = __float2bfloat16(v);
    lo = __float2bfloat16(v - __bfloat162float(hi));
}

// ---------------- K1: pool + rmsnorm + gelu -> bf16 splits directly ----------------
__global__ void k_pool(const float* __restrict__ x, const float* __restrict__ w_rms,
                       __nv_bfloat16* __restrict__ Xn, __nv_bfloat16* __restrict__ Xg) {
    int sp = blockIdx.x;
    const float* xb = x + (size_t)sp * 16 * DIN;
    __shared__ float xp[DIN];
    __shared__ float red[256];
    int t = threadIdx.x;
    float ssq = 0.f;
    for (int c = t; c < DIN; c += 256) {
        float s = 0.f;
        #pragma unroll
        for (int r = 0; r < 16; r++) s += xb[r * DIN + c];
        s *= (1.f / 16.f);
        xp[c] = s;
        ssq += s * s;
    }
    red[t] = ssq;
    __syncthreads();
    for (int o = 128; o > 0; o >>= 1) {
        if (t < o) red[t] += red[t + o];
        __syncthreads();
    }
    float scale = rsqrtf(red[0] / (float)DIN + 1e-6f);
    size_t b = (size_t)sp * K3;
    for (int c = t; c < DIN; c += 256) {
        float v = xp[c] * scale * w_rms[c];
        __nv_bfloat16 hi, lo;
        split2(v, hi, lo);
        Xn[b + c] = hi; Xn[b + DIN + c] = hi; Xn[b + 2 * DIN + c] = lo;
        float g = v * normcdff(v);
        split2(g, hi, lo);
        Xg[b + c] = hi; Xg[b + DIN + c] = hi; Xg[b + 2 * DIN + c] = lo;
    }
}

// ---------------- K2: f0 table ----------------
__global__ void k_f0(int* __restrict__ f0) {
    int d = threadIdx.x;
    if (d < SP) {
        const float log_step = (float)(log(481.0) / 32.0);
        int cnt = 0;
        #pragma unroll
        for (int f = 0; f < 32; f++) {
            float cw = (float)f + expf((float)f * log_step);
            if (cw <= (float)d) cnt++;
        }
        f0[d] = cnt;
    }
}

// ---------------- K4: transpose + split weights [hi,lo,hi] ----------------
__global__ void k_wsplit(const float* __restrict__ srcA, const float* __restrict__ srcB,
                         int Nsrc, __nv_bfloat16* __restrict__ dst) {
    __shared__ float tile[32][33];
    int t = threadIdx.x;
    int n0 = blockIdx.x * 32, k0 = blockIdx.y * 32;
    const float* src = (n0 < Nsrc) ? srcA : srcB;
    int nb = (n0 < Nsrc) ? n0 : (n0 - Nsrc);
    #pragma unroll
    for (int i = 0; i < 4; i++) {
        int r = (t >> 5) + i * 8, c = t & 31;
        tile[r][c] = src[(size_t)(k0 + r) * Nsrc + nb + c];
    }
    __syncthreads();
    #pragma unroll
    for (int i = 0; i < 4; i++) {
        int rn = (t >> 5) + i * 8;
        int kk = k0 + (t & 31);
        float v = tile[t & 31][rn];
        __nv_bfloat16 hi, lo;
        split2(v, hi, lo);
        size_t row = (size_t)(n0 + rn) * K3;
        dst[row + kk] = hi;
        dst[row + DIN + kk] = lo;
        dst[row + 2 * DIN + kk] = hi;
    }
}

// ---------------- K5: bf16 mma.sync GEMM (NT: A[m][k] . B[n][k]) ----------------
// CTA 128x128, 8 warps (2m x 4n), warp 64x32, BK=32, 3-stage cp.async.
// mode 0: q|k projection (Nout=HDTOT), mode 1: y (Nout=HD), mode 2: scores (batched z)
#define TILE_BYTES (128 * 80)
#define STAGE_BYTES (2 * TILE_BYTES)
#define MMA_SMEM (3 * STAGE_BYTES)
__global__ void __launch_bounds__(256) k_mma(
    const __nv_bfloat16* __restrict__ A, const __nv_bfloat16* __restrict__ B,
    int sA, int sB, long batA, long batB, int niter, int mode,
    float* __restrict__ o0, float* __restrict__ o1)
{
    extern __shared__ char sm[];
    uint32_t smb = smem_u32(sm);
    int t = threadIdx.x, w = t >> 5, lane = t & 31;
    int m0 = blockIdx.x * 128, n0 = blockIdx.y * 128, z = blockIdx.z;
    int wm = w >> 2, wn = w & 3;

    const __nv_bfloat16* Ab = A + batA * z + (size_t)m0 * sA;
    const __nv_bfloat16* Bb = B + batB * z + (size_t)n0 * sB;

    float c[4][4][4];
    #pragma unroll
    for (int i = 0; i < 4; i++)
        #pragma unroll
        for (int j = 0; j < 4; j++)
            #pragma unroll
            for (int e = 0; e < 4; e++) c[i][j][e] = 0.f;

    uint32_t aoff[4], boff[2];
    {
        int lr = lane & 15, lc = lane >> 4;
        #pragma unroll
        for (int mi = 0; mi < 4; mi++) aoff[mi] = (wm * 64 + mi * 16 + lr) * 80 + lc * 16;
        #pragma unroll
        for (int nj = 0; nj < 2; nj++) boff[nj] = TILE_BYTES + (wn * 32 + nj * 16 + lr) * 80 + lc * 16;
    }
    int lrow = t >> 2, lc16 = (t & 3) * 16;
    int lcol_el = (t & 3) * 8;

    #pragma unroll
    for (int s = 0; s < 2; s++) {
        if (s < niter) {
            uint32_t db = smb + s * STAGE_BYTES;
            #pragma unroll
            for (int i = 0; i < 2; i++) {
                int row = lrow + i * 64;
                uint32_t d = db + row * 80 + lc16;
                cp16(d, Ab + (size_t)row * sA + s * 32 + lcol_el);
                cp16(d + TILE_BYTES, Bb + (size_t)row * sB + s * 32 + lcol_el);
            }
        }
        CP_COMMIT();
    }

    for (int ck = 0; ck < niter; ck++) {
        int pf = ck + 2;
        if (pf < niter) {
            uint32_t db = smb + (pf % 3) * STAGE_BYTES;
            #pragma unroll
            for (int i = 0; i < 2; i++) {
                int row = lrow + i * 64;
                uint32_t d = db + row * 80 + lc16;
                cp16(d, Ab + (size_t)row * sA + pf * 32 + lcol_el);
                cp16(d + TILE_BYTES, Bb + (size_t)row * sB + pf * 32 + lcol_el);
            }
        }
        CP_COMMIT();
        CP_WAIT2();
        __syncthreads();
        uint32_t sa = smb + (ck % 3) * STAGE_BYTES;
        #pragma unroll
        for (int kk = 0; kk < 2; kk++) {
            uint32_t a[4][4], b[2][4];
            #pragma unroll
            for (int mi = 0; mi < 4; mi++) ldm_x4(a[mi], sa + aoff[mi] + kk * 32);
            #pragma unroll
            for (int nj = 0; nj < 2; nj++) ldm_x4(b[nj], sa + boff[nj] + kk * 32);
            #pragma unroll
            for (int mi = 0; mi < 4; mi++)
                #pragma unroll
                for (int ni = 0; ni < 4; ni++)
                    mma16816(c[mi][ni], a[mi], b[ni >> 1][ni & 1], b[ni >> 1][(ni & 1) + 2]);
        }
        __syncthreads();
    }

    // epilogue (coalesced fp32 only)
    int r0 = lane >> 2, c0 = (lane & 3) * 2;
    int Nout = (mode == 0) ? HDTOT : HD;
    #pragma unroll
    for (int mi = 0; mi < 4; mi++) {
        #pragma unroll
        for (int ni = 0; ni < 4; ni++) {
            #pragma unroll
            for (int half = 0; half < 2; half++) {
                int row = m0 + wm * 64 + mi * 16 + r0 + half * 8;
                int col = n0 + wn * 32 + ni * 8 + c0;
                float2 fv = make_float2(c[mi][ni][half * 2], c[mi][ni][half * 2 + 1]);
                if (mode == 2) {
                    *(float2*)&o0[((size_t)(z * SP + row)) * SP + col] = fv;
                } else {
                    bool first = col < Nout;
                    float* o = first ? o0 : o1;
                    int nn = first ? col : col - Nout;
                    *(float2*)&o[(size_t)row * Nout + nn] = fv;
                }
            }
        }
    }
}

// ---------------- K5b: coalesced split of q/k -> Qs/Ks ----------------
__global__ void k_splitqk(const float* __restrict__ q, const float* __restrict__ k,
                          __nv_bfloat16* __restrict__ Qs, __nv_bfloat16* __restrict__ Ks) {
    int idx = blockIdx.x * 256 + threadIdx.x;
    int s = idx >> 12, n = idx & 4095;
    int h = n >> 7, c = n & 127;
    size_t base = ((size_t)h * SP + s) * KH + c;
    __nv_bfloat16 hi, lo;
    split2(q[idx], hi, lo);
    Qs[base] = hi; Qs[base + 128] = lo; Qs[base + 256] = hi;
    split2(k[idx], hi, lo);
    Ks[base] = hi; Ks[base + 128] = hi; Ks[base + 256] = lo;
}

// ---------------- K6: suffix tables ----------------
__global__ void __launch_bounds__(256) k_suffix(const float* __restrict__ qk,
                                                const float* __restrict__ rbias,
                                                const float* __restrict__ W_pos,
                                                const float* __restrict__ b_pos,
                                                float* __restrict__ T) {
    extern __shared__ float smf[];
    float* ws = smf;
    float* qs = ws + 65 * 132;
    float* Ms = qs + 32 * 132;
    int h = blockIdx.y;
    int q0 = blockIdx.x * 32;
    int t = threadIdx.x;
    for (int i = t; i < 65 * 128; i += 256) {
        int f = i >> 7, c = i & 127;
        ws[f * 132 + c] = (f < 64) ? W_pos[f * HDTOT + h * HD + c] : b_pos[h * HD + c];
    }
    for (int i = t; i < 32 * 128; i += 256) {
        int r = i >> 7, c = i & 127;
        qs[r * 132 + c] = qk[(size_t)(q0 + r) * HDTOT + h * HD + c] + rbias[h * HD + c];
    }
    __syncthreads();
    for (int i = t; i < 32 * 65; i += 256) {
        int r = i / 65, f = i % 65;
        const float4* qr = (const float4*)&qs[r * 132];
        const float4* wr = (const float4*)&ws[f * 132];
        float acc = 0.f;
        #pragma unroll
        for (int c4 = 0; c4 < 32; c4++) {
            float4 a = qr[c4], b = wr[c4];
            acc += a.x * b.x + a.y * b.y + a.z * b.z + a.w * b.w;
        }
        Ms[r * 65 + f] = acc;
    }
    __syncthreads();
    for (int i = t; i < 32 * 33; i += 256) {
        int r = i / 33, j = i % 33;
        float sa = Ms[r * 65 + 64];
        float sb = 0.f;
        for (int f = j; f < 32; f++) { sa += Ms[r * 65 + f]; sb += Ms[r * 65 + 32 + f]; }
        int q = q0 + r;
        T[((j * SP + q) * NH + h) * 2] = sa;
        T[((j * SP + q) * NH + h) * 2 + 1] = sb;
    }
}

// ---------------- K7: fold suffix tables through W_pair (one block per position) ----------------
__global__ void __launch_bounds__(128) k_fold(const float* __restrict__ TQ,
                                              const float* __restrict__ TK,
                                              const float* __restrict__ Wp,
                                              float* __restrict__ RQ,
                                              float* __restrict__ RK) {
    __shared__ float tq[33 * 64], tk[33 * 64];
    int q = blockIdx.x, t = threadIdx.x;
    for (int i = t; i < 33 * 64; i += 128) {
        int j = i >> 6, r = i & 63;
        tq[i] = TQ[((size_t)j * SP + q) * 64 + r];
        tk[i] = TK[((size_t)j * SP + q) * 64 + r];
    }
    float wcol[NH];
    #pragma unroll
    for (int h = 0; h < NH; h++) wcol[h] = Wp[h * HD + t];
    __syncthreads();
    for (int j = 0; j < 33; j++) {
        float aa = 0.f, ab = 0.f, ba = 0.f, bb = 0.f;
        const float* tqj = &tq[j * 64];
        const float* tkj = &tk[j * 64];
        #pragma unroll
        for (int h = 0; h < NH; h++) {
            float w = wcol[h];
            aa += tqj[2 * h] * w;  ab += tqj[2 * h + 1] * w;
            ba += tkj[2 * h] * w;  bb += tkj[2 * h + 1] * w;
        }
        size_t ob = ((size_t)j * SP + q) * 256 + t * 2;
        RQ[ob] = aa; RQ[ob + 1] = ab;
        RK[ob] = ba; RK[ob + 1] = bb;
    }
}

// ---------------- K8: final pass (FFMA) ----------------
__global__ void __launch_bounds__(256) k_pair2(const float* __restrict__ S,
                                               const float* __restrict__ RQ,
                                               const float* __restrict__ RK,
                                               const int* __restrict__ f0tab,
                                               const float* __restrict__ Wp,
                                               const float* __restrict__ bp,
                                               const float* __restrict__ yq,
                                               const float* __restrict__ yk,
                                               float* __restrict__ out) {
    __shared__ float Sh[128 * 36];
    int t = threadIdx.x;
    int q = blockIdx.x, k0 = blockIdx.y * 128;
    for (int i = t; i < 4096; i += 256) {
        int h = i >> 7, kk = i & 127;
        Sh[kk * 36 + h] = S[(((size_t)h * SP + q) << 9) + k0 + kk];
    }
    int d = t & 127, g = t >> 7;
    float wcol[NH];
    #pragma unroll
    for (int h = 0; h < NH; h++) wcol[h] = Wp[h * HD + d];
    float base0 = bp[d] + yq[q * HD + d];
    __syncthreads();
    for (int kk = g * 64; kk < g * 64 + 64; kk++) {
        int k = k0 + kk;
        int delta = k - q;
        int dd = delta >= 0 ? delta : -delta;
        float sgn = delta > 0 ? 1.f : (delta < 0 ? -1.f : 0.f);
        int j = f0tab[dd];
        float2 rq = *(const float2*)&RQ[((size_t)j * SP + q) * 256 + d * 2];
        float2 rk = *(const float2*)&RK[((size_t)j * SP + k) * 256 + d * 2];
        float acc = base0 + yk[k * HD + d]
                  + 0.5f * (rq.x + rk.x) + 0.5f * sgn * (rq.y - rk.y);
        const float* sr = &Sh[kk * 36];
        #pragma unroll
        for (int h4 = 0; h4 < 8; h4++) {
            float4 sv = *(const float4*)&sr[h4 * 4];
            acc += sv.x * wcol[h4 * 4] + sv.y * wcol[h4 * 4 + 1] +
                   sv.z * wcol[h4 * 4 + 2] + sv.w * wcol[h4 * 4 + 3];
        }
        out[((size_t)(q * SP + k)) * HD + d] = acc;
    }
}

// ---------------- launcher ----------------
#define SUF_SMEM ((65 * 132 + 32 * 132 + 32 * 65) * 4)

extern "C" void kernel_launch(void* const* d_in, const int* in_sizes, int n_in,
                              void* d_out, int out_size) {
    const float* x      = (const float*)d_in[0];
    const float* w_rms  = (const float*)d_in[1];
    const float* W_q    = (const float*)d_in[2];
    const float* W_k    = (const float*)d_in[3];
    const float* W_pos  = (const float*)d_in[4];
    const float* b_pos  = (const float*)d_in[5];
    const float* qrb    = (const float*)d_in[6];
    const float* krb    = (const float*)d_in[7];
    const float* W_yq   = (const float*)d_in[8];
    const float* W_yk   = (const float*)d_in[9];
    const float* W_pair = (const float*)d_in[10];
    const float* b_pair = (const float*)d_in[11];
    float* out = (float*)d_out;

    float *qb, *kb, *yq, *yk, *TQ, *TK, *RQ, *RK, *Sb;
    __nv_bfloat16 *Xn, *Xg, *Ww, *Wy, *Qs, *Ks;
    int* f0;
    cudaGetSymbolAddress((void**)&qb, g_q);
    cudaGetSymbolAddress((void**)&kb, g_k);
    cudaGetSymbolAddress((void**)&yq, g_yq);
    cudaGetSymbolAddress((void**)&yk, g_yk);
    cudaGetSymbolAddress((void**)&TQ, g_TQ);
    cudaGetSymbolAddress((void**)&TK, g_TK);
    cudaGetSymbolAddress((void**)&RQ, g_RQ);
    cudaGetSymbolAddress((void**)&RK, g_RK);
    cudaGetSymbolAddress((void**)&Sb, g_S);
    cudaGetSymbolAddress((void**)&Xn, g_Xn);
    cudaGetSymbolAddress((void**)&Xg, g_Xg);
    cudaGetSymbolAddress((void**)&Ww, g_Ww);
    cudaGetSymbolAddress((void**)&Wy, g_Wy);
    cudaGetSymbolAddress((void**)&Qs, g_Qs);
    cudaGetSymbolAddress((void**)&Ks, g_Ks);
    cudaGetSymbolAddress((void**)&f0, g_f0);

    cudaFuncSetAttribute(k_mma, cudaFuncAttributeMaxDynamicSharedMemorySize, MMA_SMEM);
    cudaFuncSetAttribute(k_suffix, cudaFuncAttributeMaxDynamicSharedMemorySize, SUF_SMEM);

    k_pool<<<SP, 256>>>(x, w_rms, Xn, Xg);                                  // 1
    k_f0<<<1, 512>>>(f0);                                                   // 2
    k_wsplit<<<dim3(2 * HDTOT / 32, DIN / 32), 256>>>(W_q, W_k, HDTOT, Ww); // 3
    k_wsplit<<<dim3(2 * HD / 32, DIN / 32), 256>>>(W_yq, W_yk, HD, Wy);     // 4
    // y projection first so the qk GEMM is the 6th launch (ncu -s 5 -c 1 target)
    k_mma<<<dim3(4, 2), 256, MMA_SMEM>>>(Xg, Wy, K3, K3, 0, 0, K3 / 32, 1, yq, yk); // 5
    k_mma<<<dim3(4, 64), 256, MMA_SMEM>>>(Xn, Ww, K3, K3, 0, 0, K3 / 32, 0, qb, kb); // 6

    k_splitqk<<<SP * HDTOT / 256, 256>>>(qb, kb, Qs, Ks);

    dim3 gs(SP / 32, NH);
    k_suffix<<<gs, 256, SUF_SMEM>>>(qb, qrb, W_pos, b_pos, TQ);
    k_suffix<<<gs, 256, SUF_SMEM>>>(kb, krb, W_pos, b_pos, TK);
    k_fold<<<SP, 128>>>(TQ, TK, W_pair, RQ, RK);

    // scores: per-head 512x512x384
    k_mma<<<dim3(4, 4, NH), 256, MMA_SMEM>>>(Qs, Ks, KH, KH, (long)SP * KH, (long)SP * KH,
                                             KH / 32, 2, Sb, 0);

    k_pair2<<<dim3(SP, 4), 256>>>(Sb, RQ, RK, f0, W_pair, b_pair, yq, yk, out);
}

// round 6
// speedup vs baseline: 2.3577x; 1.1856x over previous
#include <cuda_runtime.h>
#include <cuda_bf16.h>
#include <math.h>
#include <stdint.h>

#define SP    512
#define DIN   1536
#define NH    32
#define HD    128
#define HDTOT 4096
#define K3    4608   // 3*DIN
#define KH    384    // 3*HD

// ---------------- scratch ----------------
__device__ __nv_bfloat16 g_Xn[SP*K3];       // x_norm split [hi,hi,lo]
__device__ __nv_bfloat16 g_Xg[SP*K3];       // x_gelu split [hi,hi,lo]
__device__ __nv_bfloat16 g_Ww[(size_t)2*HDTOT*K3]; // Wq|Wk transposed, split [hi,lo,hi]
__device__ __nv_bfloat16 g_Wy[2*HD*K3];     // Wyq|Wyk transposed, split [hi,lo,hi]
__device__ float g_q[SP*HDTOT];
__device__ float g_k[SP*HDTOT];
__device__ float g_yq[SP*HD];
__device__ float g_yk[SP*HD];
__device__ __nv_bfloat16 g_Qs[(size_t)NH*SP*KH];  // [h][s][384] split [hi,lo,hi]
__device__ __nv_bfloat16 g_Ks[(size_t)NH*SP*KH];  // [h][s][384] split [hi,hi,lo]
__device__ float g_S[(size_t)NH*SP*SP];     // scores [h][q][k]
__device__ float g_TQ[33*SP*NH*2];
__device__ float g_TK[33*SP*NH*2];
__device__ float g_RQ[33*SP*HD*2];
__device__ float g_RK[33*SP*HD*2];
__device__ int   g_f0[SP];

// ---------------- helpers ----------------
__device__ __forceinline__ uint32_t smem_u32(const void* p) {
    uint32_t a;
    asm("{ .reg .u64 t; cvta.to.shared.u64 t, %1; cvt.u32.u64 %0, t; }" : "=r"(a) : "l"(p));
    return a;
}
__device__ __forceinline__ void cp16(uint32_t dst, const void* src) {
    asm volatile("cp.async.cg.shared.global [%0], [%1], 16;" :: "r"(dst), "l"(src));
}
#define CP_COMMIT() asm volatile("cp.async.commit_group;" ::: "memory")
#define CP_WAIT2()  asm volatile("cp.async.wait_group 2;" ::: "memory")

__device__ __forceinline__ void ldm_x4(uint32_t* r, uint32_t addr) {
    asm volatile("ldmatrix.sync.aligned.m8n8.x4.shared.b16 {%0,%1,%2,%3}, [%4];"
                 : "=r"(r[0]), "=r"(r[1]), "=r"(r[2]), "=r"(r[3]) : "r"(addr));
}
__device__ __forceinline__ void mma16816(float* c, const uint32_t* a, uint32_t b0, uint32_t b1) {
    asm volatile("mma.sync.aligned.m16n8k16.row.col.f32.bf16.bf16.f32 "
                 "{%0,%1,%2,%3}, {%4,%5,%6,%7}, {%8,%9}, {%0,%1,%2,%3};"
                 : "+f"(c[0]), "+f"(c[1]), "+f"(c[2]), "+f"(c[3])
                 : "r"(a[0]), "r"(a[1]), "r"(a[2]), "r"(a[3]), "r"(b0), "r"(b1));
}
__device__ __forceinline__ void split2(float v, __nv_bfloat16& hi, __nv_bfloat16& lo) {
    hi = __float2bfloat16(v);
    lo = __float2bfloat16(v - __bfloat162float(hi));
}

#define TILE_BYTES (128 * 80)
#define STAGE_BYTES (2 * TILE_BYTES)
#define MMA_SMEM (3 * STAGE_BYTES)

// shared mainloop: computes c[4][4][4] for a 128x128 tile from Ab/Bb (NT, K=niter*32)
__device__ __forceinline__ void mma_mainloop(
    char* sm, uint32_t smb, const __nv_bfloat16* __restrict__ Ab,
    const __nv_bfloat16* __restrict__ Bb, int sA, int sB, int niter,
    int t, int lane, int wm, int wn, float c[4][4][4])
{
    uint32_t aoff[4], boff[2];
    {
        int lr = lane & 15, lc = lane >> 4;
        #pragma unroll
        for (int mi = 0; mi < 4; mi++) aoff[mi] = (wm * 64 + mi * 16 + lr) * 80 + lc * 16;
        #pragma unroll
        for (int nj = 0; nj < 2; nj++) boff[nj] = TILE_BYTES + (wn * 32 + nj * 16 + lr) * 80 + lc * 16;
    }
    int lrow = t >> 2, lc16 = (t & 3) * 16;
    int lcol_el = (t & 3) * 8;

    #pragma unroll
    for (int s = 0; s < 2; s++) {
        if (s < niter) {
            uint32_t db = smb + s * STAGE_BYTES;
            #pragma unroll
            for (int i = 0; i < 2; i++) {
                int row = lrow + i * 64;
                uint32_t d = db + row * 80 + lc16;
                cp16(d, Ab + (size_t)row * sA + s * 32 + lcol_el);
                cp16(d + TILE_BYTES, Bb + (size_t)row * sB + s * 32 + lcol_el);
            }
        }
        CP_COMMIT();
    }

    for (int ck = 0; ck < niter; ck++) {
        int pf = ck + 2;
        if (pf < niter) {
            uint32_t db = smb + (pf % 3) * STAGE_BYTES;
            #pragma unroll
            for (int i = 0; i < 2; i++) {
                int row = lrow + i * 64;
                uint32_t d = db + row * 80 + lc16;
                cp16(d, Ab + (size_t)row * sA + pf * 32 + lcol_el);
                cp16(d + TILE_BYTES, Bb + (size_t)row * sB + pf * 32 + lcol_el);
            }
        }
        CP_COMMIT();
        CP_WAIT2();
        __syncthreads();
        uint32_t sa = smb + (ck % 3) * STAGE_BYTES;
        #pragma unroll
        for (int kk = 0; kk < 2; kk++) {
            uint32_t a[4][4], b[2][4];
            #pragma unroll
            for (int mi = 0; mi < 4; mi++) ldm_x4(a[mi], sa + aoff[mi] + kk * 32);
            #pragma unroll
            for (int nj = 0; nj < 2; nj++) ldm_x4(b[nj], sa + boff[nj] + kk * 32);
            #pragma unroll
            for (int mi = 0; mi < 4; mi++)
                #pragma unroll
                for (int ni = 0; ni < 4; ni++)
                    mma16816(c[mi][ni], a[mi], b[ni >> 1][ni & 1], b[ni >> 1][(ni & 1) + 2]);
        }
        __syncthreads();
    }
}

// ---------------- K1: pool + rmsnorm + gelu -> bf16 splits directly ----------------
__global__ void k_pool(const float* __restrict__ x, const float* __restrict__ w_rms,
                       __nv_bfloat16* __restrict__ Xn, __nv_bfloat16* __restrict__ Xg) {
    int sp = blockIdx.x;
    const float* xb = x + (size_t)sp * 16 * DIN;
    __shared__ float xp[DIN];
    __shared__ float red[256];
    int t = threadIdx.x;
    float ssq = 0.f;
    for (int c = t; c < DIN; c += 256) {
        float s = 0.f;
        #pragma unroll
        for (int r = 0; r < 16; r++) s += xb[r * DIN + c];
        s *= (1.f / 16.f);
        xp[c] = s;
        ssq += s * s;
    }
    red[t] = ssq;
    __syncthreads();
    for (int o = 128; o > 0; o >>= 1) {
        if (t < o) red[t] += red[t + o];
        __syncthreads();
    }
    float scale = rsqrtf(red[0] / (float)DIN + 1e-6f);
    size_t b = (size_t)sp * K3;
    for (int c = t; c < DIN; c += 256) {
        float v = xp[c] * scale * w_rms[c];
        __nv_bfloat16 hi, lo;
        split2(v, hi, lo);
        Xn[b + c] = hi; Xn[b + DIN + c] = hi; Xn[b + 2 * DIN + c] = lo;
        float g = v * normcdff(v);
        split2(g, hi, lo);
        Xg[b + c] = hi; Xg[b + DIN + c] = hi; Xg[b + 2 * DIN + c] = lo;
    }
}

// ---------------- K2: f0 table ----------------
__global__ void k_f0(int* __restrict__ f0) {
    int d = threadIdx.x;
    if (d < SP) {
        const float log_step = (float)(log(481.0) / 32.0);
        int cnt = 0;
        #pragma unroll
        for (int f = 0; f < 32; f++) {
            float cw = (float)f + expf((float)f * log_step);
            if (cw <= (float)d) cnt++;
        }
        f0[d] = cnt;
    }
}

// ---------------- K4: transpose + split weights [hi,lo,hi] ----------------
__global__ void k_wsplit(const float* __restrict__ srcA, const float* __restrict__ srcB,
                         int Nsrc, __nv_bfloat16* __restrict__ dst) {
    __shared__ float tile[32][33];
    int t = threadIdx.x;
    int n0 = blockIdx.x * 32, k0 = blockIdx.y * 32;
    const float* src = (n0 < Nsrc) ? srcA : srcB;
    int nb = (n0 < Nsrc) ? n0 : (n0 - Nsrc);
    #pragma unroll
    for (int i = 0; i < 4; i++) {
        int r = (t >> 5) + i * 8, c = t & 31;
        tile[r][c] = src[(size_t)(k0 + r) * Nsrc + nb + c];
    }
    __syncthreads();
    #pragma unroll
    for (int i = 0; i < 4; i++) {
        int rn = (t >> 5) + i * 8;
        int kk = k0 + (t & 31);
        float v = tile[t & 31][rn];
        __nv_bfloat16 hi, lo;
        split2(v, hi, lo);
        size_t row = (size_t)(n0 + rn) * K3;
        dst[row + kk] = hi;
        dst[row + DIN + kk] = lo;
        dst[row + 2 * DIN + kk] = hi;
    }
}

// ---------------- K5: fused projection GEMM (q|k and y in one launch) ----------------
// blocks 0..255: (Xn x Ww) -> q|k ; blocks 256..263: (Xg x Wy) -> yq|yk
__global__ void __launch_bounds__(256) k_proj(
    const __nv_bfloat16* __restrict__ Xn, const __nv_bfloat16* __restrict__ Xg,
    const __nv_bfloat16* __restrict__ Ww, const __nv_bfloat16* __restrict__ Wy,
    float* __restrict__ q, float* __restrict__ k,
    float* __restrict__ yq, float* __restrict__ yk)
{
    extern __shared__ char sm[];
    uint32_t smb = smem_u32(sm);
    int t = threadIdx.x, w = t >> 5, lane = t & 31;
    int wm = w >> 2, wn = w & 3;
    int bid = blockIdx.x;
    int mt, nt;
    if (bid < 256) { mt = bid & 3; nt = bid >> 2; }
    else { int e = bid - 256; mt = 4 + (e & 3); nt = 64 + (e >> 2); }

    const __nv_bfloat16* Ab = (mt < 4) ? (Xn + (size_t)mt * 128 * K3)
                                       : (Xg + (size_t)(mt - 4) * 128 * K3);
    const __nv_bfloat16* Bb = (nt < 64) ? (Ww + (size_t)nt * 128 * K3)
                                        : (Wy + (size_t)(nt - 64) * 128 * K3);

    float c[4][4][4];
    #pragma unroll
    for (int i = 0; i < 4; i++)
        #pragma unroll
        for (int j = 0; j < 4; j++)
            #pragma unroll
            for (int e = 0; e < 4; e++) c[i][j][e] = 0.f;

    mma_mainloop(sm, smb, Ab, Bb, K3, K3, K3 / 32, t, lane, wm, wn, c);

    int r0 = lane >> 2, c0 = (lane & 3) * 2;
    int srow0 = (mt < 4 ? mt : mt - 4) * 128;
    #pragma unroll
    for (int mi = 0; mi < 4; mi++) {
        #pragma unroll
        for (int ni = 0; ni < 4; ni++) {
            #pragma unroll
            for (int half = 0; half < 2; half++) {
                int s = srow0 + wm * 64 + mi * 16 + r0 + half * 8;
                int colL = wn * 32 + ni * 8 + c0;       // 0..127 within tile
                float2 fv = make_float2(c[mi][ni][half * 2], c[mi][ni][half * 2 + 1]);
                if (nt < 64) {
                    int col = nt * 128 + colL;          // 0..8191
                    bool isQ = col < HDTOT;
                    float* o = isQ ? q : k;
                    int nn = isQ ? col : col - HDTOT;
                    *(float2*)&o[(size_t)s * HDTOT + nn] = fv;
                } else {
                    int cy = (nt - 64) * 128 + colL;    // 0..255
                    float* o = (cy < HD) ? yq : yk;
                    int nn = (cy < HD) ? cy : cy - HD;
                    *(float2*)&o[(size_t)s * HD + nn] = fv;
                }
            }
        }
    }
}

// ---------------- K5s: scores GEMM (batched over heads) ----------------
__global__ void __launch_bounds__(256) k_scores(
    const __nv_bfloat16* __restrict__ Qs, const __nv_bfloat16* __restrict__ Ks,
    float* __restrict__ S)
{
    extern __shared__ char sm[];
    uint32_t smb = smem_u32(sm);
    int t = threadIdx.x, w = t >> 5, lane = t & 31;
    int wm = w >> 2, wn = w & 3;
    int m0 = blockIdx.x * 128, n0 = blockIdx.y * 128, z = blockIdx.z;

    const __nv_bfloat16* Ab = Qs + (size_t)z * SP * KH + (size_t)m0 * KH;
    const __nv_bfloat16* Bb = Ks + (size_t)z * SP * KH + (size_t)n0 * KH;

    float c[4][4][4];
    #pragma unroll
    for (int i = 0; i < 4; i++)
        #pragma unroll
        for (int j = 0; j < 4; j++)
            #pragma unroll
            for (int e = 0; e < 4; e++) c[i][j][e] = 0.f;

    mma_mainloop(sm, smb, Ab, Bb, KH, KH, KH / 32, t, lane, wm, wn, c);

    int r0 = lane >> 2, c0 = (lane & 3) * 2;
    #pragma unroll
    for (int mi = 0; mi < 4; mi++) {
        #pragma unroll
        for (int ni = 0; ni < 4; ni++) {
            #pragma unroll
            for (int half = 0; half < 2; half++) {
                int row = m0 + wm * 64 + mi * 16 + r0 + half * 8;
                int col = n0 + wn * 32 + ni * 8 + c0;
                float2 fv = make_float2(c[mi][ni][half * 2], c[mi][ni][half * 2 + 1]);
                *(float2*)&S[((size_t)(z * SP + row)) * SP + col] = fv;
            }
        }
    }
}

// ---------------- K5b: coalesced split of q/k -> Qs/Ks ----------------
__global__ void k_splitqk(const float* __restrict__ q, const float* __restrict__ k,
                          __nv_bfloat16* __restrict__ Qs, __nv_bfloat16* __restrict__ Ks) {
    int idx = blockIdx.x * 256 + threadIdx.x;
    int s = idx >> 12, n = idx & 4095;
    int h = n >> 7, c = n & 127;
    size_t base = ((size_t)h * SP + s) * KH + c;
    __nv_bfloat16 hi, lo;
    split2(q[idx], hi, lo);
    Qs[base] = hi; Qs[base + 128] = lo; Qs[base + 256] = hi;
    split2(k[idx], hi, lo);
    Ks[base] = hi; Ks[base + 128] = hi; Ks[base + 256] = lo;
}

// ---------------- K6: suffix tables ----------------
__global__ void __launch_bounds__(256) k_suffix(const float* __restrict__ qk,
                                                const float* __restrict__ rbias,
                                                const float* __restrict__ W_pos,
                                                const float* __restrict__ b_pos,
                                                float* __restrict__ T) {
    extern __shared__ float smf[];
    float* ws = smf;
    float* qs = ws + 65 * 132;
    float* Ms = qs + 32 * 132;
    int h = blockIdx.y;
    int q0 = blockIdx.x * 32;
    int t = threadIdx.x;
    for (int i = t; i < 65 * 128; i += 256) {
        int f = i >> 7, c = i & 127;
        ws[f * 132 + c] = (f < 64) ? W_pos[f * HDTOT + h * HD + c] : b_pos[h * HD + c];
    }
    for (int i = t; i < 32 * 128; i += 256) {
        int r = i >> 7, c = i & 127;
        qs[r * 132 + c] = qk[(size_t)(q0 + r) * HDTOT + h * HD + c] + rbias[h * HD + c];
    }
    __syncthreads();
    for (int i = t; i < 32 * 65; i += 256) {
        int r = i / 65, f = i % 65;
        const float4* qr = (const float4*)&qs[r * 132];
        const float4* wr = (const float4*)&ws[f * 132];
        float acc = 0.f;
        #pragma unroll
        for (int c4 = 0; c4 < 32; c4++) {
            float4 a = qr[c4], b = wr[c4];
            acc += a.x * b.x + a.y * b.y + a.z * b.z + a.w * b.w;
        }
        Ms[r * 65 + f] = acc;
    }
    __syncthreads();
    for (int i = t; i < 32 * 33; i += 256) {
        int r = i / 33, j = i % 33;
        float sa = Ms[r * 65 + 64];
        float sb = 0.f;
        for (int f = j; f < 32; f++) { sa += Ms[r * 65 + f]; sb += Ms[r * 65 + 32 + f]; }
        int q = q0 + r;
        T[((j * SP + q) * NH + h) * 2] = sa;
        T[((j * SP + q) * NH + h) * 2 + 1] = sb;
    }
}

// ---------------- K7: fold suffix tables through W_pair ----------------
__global__ void __launch_bounds__(128) k_fold(const float* __restrict__ TQ,
                                              const float* __restrict__ TK,
                                              const float* __restrict__ Wp,
                                              float* __restrict__ RQ,
                                              float* __restrict__ RK) {
    __shared__ float tq[33 * 64], tk[33 * 64];
    int q = blockIdx.x, t = threadIdx.x;
    for (int i = t; i < 33 * 64; i += 128) {
        int j = i >> 6, r = i & 63;
        tq[i] = TQ[((size_t)j * SP + q) * 64 + r];
        tk[i] = TK[((size_t)j * SP + q) * 64 + r];
    }
    float wcol[NH];
    #pragma unroll
    for (int h = 0; h < NH; h++) wcol[h] = Wp[h * HD + t];
    __syncthreads();
    for (int j = 0; j < 33; j++) {
        float aa = 0.f, ab = 0.f, ba = 0.f, bb = 0.f;
        const float* tqj = &tq[j * 64];
        const float* tkj = &tk[j * 64];
        #pragma unroll
        for (int h = 0; h < NH; h++) {
            float w = wcol[h];
            aa += tqj[2 * h] * w;  ab += tqj[2 * h + 1] * w;
            ba += tkj[2 * h] * w;  bb += tkj[2 * h + 1] * w;
        }
        size_t ob = ((size_t)j * SP + q) * 256 + t * 2;
        RQ[ob] = aa; RQ[ob + 1] = ab;
        RK[ob] = ba; RK[ob + 1] = bb;
    }
}

// ---------------- K8: final pass (FFMA) ----------------
__global__ void __launch_bounds__(256) k_pair2(const float* __restrict__ S,
                                               const float* __restrict__ RQ,
                                               const float* __restrict__ RK,
                                               const int* __restrict__ f0tab,
                                               const float* __restrict__ Wp,
                                               const float* __restrict__ bp,
                                               const float* __restrict__ yq,
                                               const float* __restrict__ yk,
                                               float* __restrict__ out) {
    __shared__ float Sh[128 * 36];
    int t = threadIdx.x;
    int q = blockIdx.x, k0 = blockIdx.y * 128;
    for (int i = t; i < 4096; i += 256) {
        int h = i >> 7, kk = i & 127;
        Sh[kk * 36 + h] = S[(((size_t)h * SP + q) << 9) + k0 + kk];
    }
    int d = t & 127, g = t >> 7;
    float wcol[NH];
    #pragma unroll
    for (int h = 0; h < NH; h++) wcol[h] = Wp[h * HD + d];
    float base0 = bp[d] + yq[q * HD + d];
    __syncthreads();
    for (int kk = g * 64; kk < g * 64 + 64; kk++) {
        int k = k0 + kk;
        int delta = k - q;
        int dd = delta >= 0 ? delta : -delta;
        float sgn = delta > 0 ? 1.f : (delta < 0 ? -1.f : 0.f);
        int j = f0tab[dd];
        float2 rq = *(const float2*)&RQ[((size_t)j * SP + q) * 256 + d * 2];
        float2 rk = *(const float2*)&RK[((size_t)j * SP + k) * 256 + d * 2];
        float acc = base0 + yk[k * HD + d]
                  + 0.5f * (rq.x + rk.x) + 0.5f * sgn * (rq.y - rk.y);
        const float* sr = &Sh[kk * 36];
        #pragma unroll
        for (int h4 = 0; h4 < 8; h4++) {
            float4 sv = *(const float4*)&sr[h4 * 4];
            acc += sv.x * wcol[h4 * 4] + sv.y * wcol[h4 * 4 + 1] +
                   sv.z * wcol[h4 * 4 + 2] + sv.w * wcol[h4 * 4 + 3];
        }
        out[((size_t)(q * SP + k)) * HD + d] = acc;
    }
}

// ---------------- launcher ----------------
#define SUF_SMEM ((65 * 132 + 32 * 132 + 32 * 65) * 4)

extern "C" void kernel_launch(void* const* d_in, const int* in_sizes, int n_in,
                              void* d_out, int out_size) {
    const float* x      = (const float*)d_in[0];
    const float* w_rms  = (const float*)d_in[1];
    const float* W_q    = (const float*)d_in[2];
    const float* W_k    = (const float*)d_in[3];
    const float* W_pos  = (const float*)d_in[4];
    const float* b_pos  = (const float*)d_in[5];
    const float* qrb    = (const float*)d_in[6];
    const float* krb    = (const float*)d_in[7];
    const float* W_yq   = (const float*)d_in[8];
    const float* W_yk   = (const float*)d_in[9];
    const float* W_pair = (const float*)d_in[10];
    const float* b_pair = (const float*)d_in[11];
    float* out = (float*)d_out;

    float *qb, *kb, *yq, *yk, *TQ, *TK, *RQ, *RK, *Sb;
    __nv_bfloat16 *Xn, *Xg, *Ww, *Wy, *Qs, *Ks;
    int* f0;
    cudaGetSymbolAddress((void**)&qb, g_q);
    cudaGetSymbolAddress((void**)&kb, g_k);
    cudaGetSymbolAddress((void**)&yq, g_yq);
    cudaGetSymbolAddress((void**)&yk, g_yk);
    cudaGetSymbolAddress((void**)&TQ, g_TQ);
    cudaGetSymbolAddress((void**)&TK, g_TK);
    cudaGetSymbolAddress((void**)&RQ, g_RQ);
    cudaGetSymbolAddress((void**)&RK, g_RK);
    cudaGetSymbolAddress((void**)&Sb, g_S);
    cudaGetSymbolAddress((void**)&Xn, g_Xn);
    cudaGetSymbolAddress((void**)&Xg, g_Xg);
    cudaGetSymbolAddress((void**)&Ww, g_Ww);
    cudaGetSymbolAddress((void**)&Wy, g_Wy);
    cudaGetSymbolAddress((void**)&Qs, g_Qs);
    cudaGetSymbolAddress((void**)&Ks, g_Ks);
    cudaGetSymbolAddress((void**)&f0, g_f0);

    cudaFuncSetAttribute(k_proj, cudaFuncAttributeMaxDynamicSharedMemorySize, MMA_SMEM);
    cudaFuncSetAttribute(k_scores, cudaFuncAttributeMaxDynamicSharedMemorySize, MMA_SMEM);
    cudaFuncSetAttribute(k_suffix, cudaFuncAttributeMaxDynamicSharedMemorySize, SUF_SMEM);

    k_pool<<<SP, 256>>>(x, w_rms, Xn, Xg);                                  // idx 0
    k_wsplit<<<dim3(2 * HD / 32, DIN / 32), 256>>>(W_yq, W_yk, HD, Wy);     // idx 1
    k_wsplit<<<dim3(2 * HDTOT / 32, DIN / 32), 256>>>(W_q, W_k, HDTOT, Ww); // idx 2
    k_proj<<<264, 256, MMA_SMEM>>>(Xn, Xg, Ww, Wy, qb, kb, yq, yk);         // idx 3 (profiled)
    k_f0<<<1, 512>>>(f0);                                                   // idx 4

    k_splitqk<<<SP * HDTOT / 256, 256>>>(qb, kb, Qs, Ks);

    dim3 gs(SP / 32, NH);
    k_suffix<<<gs, 256, SUF_SMEM>>>(qb, qrb, W_pos, b_pos, TQ);
    k_suffix<<<gs, 256, SUF_SMEM>>>(kb, krb, W_pos, b_pos, TK);
    k_fold<<<SP, 128>>>(TQ, TK, W_pair, RQ, RK);

    k_scores<<<dim3(4, 4, NH), 256, MMA_SMEM>>>(Qs, Ks, Sb);

    k_pair2<<<dim3(SP, 4), 256>>>(Sb, RQ, RK, f0, W_pair, b_pair, yq, yk, out);
}

// round 7
// speedup vs baseline: 2.4817x; 1.0526x over previous
#include <cuda_runtime.h>
#include <cuda_bf16.h>
#include <math.h>
#include <stdint.h>

#define SP    512
#define DIN   1536
#define NH    32
#define HD    128
#define HDTOT 4096
#define K3    4608   // 3*DIN
#define KH    384    // 3*HD

// ---------------- scratch ----------------
__device__ __nv_bfloat16 g_Xn[SP*K3];
__device__ __nv_bfloat16 g_Xg[SP*K3];
__device__ __nv_bfloat16 g_Ww[(size_t)2*HDTOT*K3];
__device__ __nv_bfloat16 g_Wy[2*HD*K3];
__device__ float g_q[SP*HDTOT];
__device__ float g_k[SP*HDTOT];
__device__ float g_yq[SP*HD];
__device__ float g_yk[SP*HD];
__device__ __nv_bfloat16 g_Qs[(size_t)NH*SP*KH];
__device__ __nv_bfloat16 g_Ks[(size_t)NH*SP*KH];
__device__ float g_S[(size_t)NH*SP*SP];
__device__ float g_TQ[33*SP*NH*2];
__device__ float g_TK[33*SP*NH*2];
__device__ float g_RQ[33*SP*HD*2];
__device__ float g_RK[33*SP*HD*2];
__device__ int   g_f0[SP];

// ---------------- helpers ----------------
__device__ __forceinline__ uint32_t smem_u32(const void* p) {
    uint32_t a;
    asm("{ .reg .u64 t; cvta.to.shared.u64 t, %1; cvt.u32.u64 %0, t; }" : "=r"(a) : "l"(p));
    return a;
}
__device__ __forceinline__ void cp16(uint32_t dst, const void* src) {
    asm volatile("cp.async.cg.shared.global [%0], [%1], 16;" :: "r"(dst), "l"(src));
}
#define CP_COMMIT() asm volatile("cp.async.commit_group;" ::: "memory")
#define CP_WAIT1()  asm volatile("cp.async.wait_group 1;" ::: "memory")

__device__ __forceinline__ void ldm_x4(uint32_t* r, uint32_t addr) {
    asm volatile("ldmatrix.sync.aligned.m8n8.x4.shared.b16 {%0,%1,%2,%3}, [%4];"
                 : "=r"(r[0]), "=r"(r[1]), "=r"(r[2]), "=r"(r[3]) : "r"(addr));
}
__device__ __forceinline__ void mma16816(float* c, const uint32_t* a, uint32_t b0, uint32_t b1) {
    asm volatile("mma.sync.aligned.m16n8k16.row.col.f32.bf16.bf16.f32 "
                 "{%0,%1,%2,%3}, {%4,%5,%6,%7}, {%8,%9}, {%0,%1,%2,%3};"
                 : "+f"(c[0]), "+f"(c[1]), "+f"(c[2]), "+f"(c[3])
                 : "r"(a[0]), "r"(a[1]), "r"(a[2]), "r"(a[3]), "r"(b0), "r"(b1));
}
__device__ __forceinline__ void split2(float v, __nv_bfloat16& hi, __nv_bfloat16& lo) {
    hi = __float2bfloat16(v);
    lo = __float2bfloat16(v - __bfloat162float(hi));
}

// BK=64 tiles: 128 rows x 72 bf16 (64 data + 8 pad) = 144 B/row
#define A_TILE 18432                 // 128 * 144
#define STAGE_BYTES (2 * A_TILE)     // 36864
#define MMA_SMEM (3 * STAGE_BYTES)   // 110592

// mainloop: 128x128 tile, NT, K = niter*64, one barrier per iteration
__device__ __forceinline__ void mma_mainloop(
    uint32_t smb, const __nv_bfloat16* __restrict__ Ab,
    const __nv_bfloat16* __restrict__ Bb, int sA, int sB, int niter,
    int t, int lane, int wm, int wn, float c[4][4][4])
{
    uint32_t aoff[4], boff[2];
    {
        int lr = lane & 15, lc = lane >> 4;
        #pragma unroll
        for (int mi = 0; mi < 4; mi++) aoff[mi] = (wm * 64 + mi * 16 + lr) * 144 + lc * 16;
        #pragma unroll
        for (int nj = 0; nj < 2; nj++) boff[nj] = A_TILE + (wn * 32 + nj * 16 + lr) * 144 + lc * 16;
    }
    int lrow = t >> 3;            // 0..31
    int lc16 = (t & 7) * 16;      // byte col in row (0..112)
    int lcol_el = (t & 7) * 8;    // element col

    // prologue: stages 0,1
    #pragma unroll
    for (int s = 0; s < 2; s++) {
        uint32_t db = smb + s * STAGE_BYTES;
        #pragma unroll
        for (int i = 0; i < 4; i++) {
            int row = lrow + i * 32;
            cp16(db + row * 144 + lc16, Ab + (size_t)row * sA + s * 64 + lcol_el);
            cp16(db + A_TILE + row * 144 + lc16, Bb + (size_t)row * sB + s * 64 + lcol_el);
        }
        CP_COMMIT();
    }

    for (int ck = 0; ck < niter; ck++) {
        CP_WAIT1();
        __syncthreads();   // all warps done with compute(ck-1); stage ck ready
        int pf = ck + 2;
        if (pf < niter) {  // writes stage (ck+2)%3 == (ck-1)%3, safe after barrier
            uint32_t db = smb + (pf % 3) * STAGE_BYTES;
            #pragma unroll
            for (int i = 0; i < 4; i++) {
                int row = lrow + i * 32;
                cp16(db + row * 144 + lc16, Ab + (size_t)row * sA + pf * 64 + lcol_el);
                cp16(db + A_TILE + row * 144 + lc16, Bb + (size_t)row * sB + pf * 64 + lcol_el);
            }
        }
        CP_COMMIT();
        uint32_t sa = smb + (ck % 3) * STAGE_BYTES;
        #pragma unroll
        for (int kk = 0; kk < 4; kk++) {
            uint32_t a[4][4], b[2][4];
            #pragma unroll
            for (int mi = 0; mi < 4; mi++) ldm_x4(a[mi], sa + aoff[mi] + kk * 32);
            #pragma unroll
            for (int nj = 0; nj < 2; nj++) ldm_x4(b[nj], sa + boff[nj] + kk * 32);
            #pragma unroll
            for (int mi = 0; mi < 4; mi++)
                #pragma unroll
                for (int ni = 0; ni < 4; ni++)
                    mma16816(c[mi][ni], a[mi], b[ni >> 1][ni & 1], b[ni >> 1][(ni & 1) + 2]);
        }
    }
}

// ---------------- K1: pool + rmsnorm + gelu -> bf16 splits ----------------
__global__ void k_pool(const float* __restrict__ x, const float* __restrict__ w_rms,
                       __nv_bfloat16* __restrict__ Xn, __nv_bfloat16* __restrict__ Xg) {
    int sp = blockIdx.x;
    const float* xb = x + (size_t)sp * 16 * DIN;
    __shared__ float xp[DIN];
    __shared__ float red[256];
    int t = threadIdx.x;
    float ssq = 0.f;
    for (int c = t; c < DIN; c += 256) {
        float s = 0.f;
        #pragma unroll
        for (int r = 0; r < 16; r++) s += xb[r * DIN + c];
        s *= (1.f / 16.f);
        xp[c] = s;
        ssq += s * s;
    }
    red[t] = ssq;
    __syncthreads();
    for (int o = 128; o > 0; o >>= 1) {
        if (t < o) red[t] += red[t + o];
        __syncthreads();
    }
    float scale = rsqrtf(red[0] / (float)DIN + 1e-6f);
    size_t b = (size_t)sp * K3;
    for (int c = t; c < DIN; c += 256) {
        float v = xp[c] * scale * w_rms[c];
        __nv_bfloat16 hi, lo;
        split2(v, hi, lo);
        Xn[b + c] = hi; Xn[b + DIN + c] = hi; Xn[b + 2 * DIN + c] = lo;
        float g = v * normcdff(v);
        split2(g, hi, lo);
        Xg[b + c] = hi; Xg[b + DIN + c] = hi; Xg[b + 2 * DIN + c] = lo;
    }
}

// ---------------- K2: f0 table ----------------
__global__ void k_f0(int* __restrict__ f0) {
    int d = threadIdx.x;
    if (d < SP) {
        const float log_step = (float)(log(481.0) / 32.0);
        int cnt = 0;
        #pragma unroll
        for (int f = 0; f < 32; f++) {
            float cw = (float)f + expf((float)f * log_step);
            if (cw <= (float)d) cnt++;
        }
        f0[d] = cnt;
    }
}

// ---------------- K4: transpose + split weights [hi,lo,hi] ----------------
__global__ void k_wsplit(const float* __restrict__ srcA, const float* __restrict__ srcB,
                         int Nsrc, __nv_bfloat16* __restrict__ dst) {
    __shared__ float tile[32][33];
    int t = threadIdx.x;
    int n0 = blockIdx.x * 32, k0 = blockIdx.y * 32;
    const float* src = (n0 < Nsrc) ? srcA : srcB;
    int nb = (n0 < Nsrc) ? n0 : (n0 - Nsrc);
    #pragma unroll
    for (int i = 0; i < 4; i++) {
        int r = (t >> 5) + i * 8, c = t & 31;
        tile[r][c] = src[(size_t)(k0 + r) * Nsrc + nb + c];
    }
    __syncthreads();
    #pragma unroll
    for (int i = 0; i < 4; i++) {
        int rn = (t >> 5) + i * 8;
        int kk = k0 + (t & 31);
        float v = tile[t & 31][rn];
        __nv_bfloat16 hi, lo;
        split2(v, hi, lo);
        size_t row = (size_t)(n0 + rn) * K3;
        dst[row + kk] = hi;
        dst[row + DIN + kk] = lo;
        dst[row + 2 * DIN + kk] = hi;
    }
}

// ---------------- K5: fused projection GEMM ----------------
__global__ void __launch_bounds__(256) k_proj(
    const __nv_bfloat16* __restrict__ Xn, const __nv_bfloat16* __restrict__ Xg,
    const __nv_bfloat16* __restrict__ Ww, const __nv_bfloat16* __restrict__ Wy,
    float* __restrict__ q, float* __restrict__ k,
    float* __restrict__ yq, float* __restrict__ yk)
{
    extern __shared__ char sm[];
    uint32_t smb = smem_u32(sm);
    int t = threadIdx.x, w = t >> 5, lane = t & 31;
    int wm = w >> 2, wn = w & 3;
    int bid = blockIdx.x;
    int mt, nt;
    if (bid < 256) { mt = bid & 3; nt = bid >> 2; }
    else { int e = bid - 256; mt = 4 + (e & 3); nt = 64 + (e >> 2); }

    const __nv_bfloat16* Ab = (mt < 4) ? (Xn + (size_t)mt * 128 * K3)
                                       : (Xg + (size_t)(mt - 4) * 128 * K3);
    const __nv_bfloat16* Bb = (nt < 64) ? (Ww + (size_t)nt * 128 * K3)
                                        : (Wy + (size_t)(nt - 64) * 128 * K3);

    float c[4][4][4];
    #pragma unroll
    for (int i = 0; i < 4; i++)
        #pragma unroll
        for (int j = 0; j < 4; j++)
            #pragma unroll
            for (int e = 0; e < 4; e++) c[i][j][e] = 0.f;

    mma_mainloop(smb, Ab, Bb, K3, K3, K3 / 64, t, lane, wm, wn, c);

    int r0 = lane >> 2, c0 = (lane & 3) * 2;
    int srow0 = (mt < 4 ? mt : mt - 4) * 128;
    #pragma unroll
    for (int mi = 0; mi < 4; mi++) {
        #pragma unroll
        for (int ni = 0; ni < 4; ni++) {
            #pragma unroll
            for (int half = 0; half < 2; half++) {
                int s = srow0 + wm * 64 + mi * 16 + r0 + half * 8;
                int colL = wn * 32 + ni * 8 + c0;
                float2 fv = make_float2(c[mi][ni][half * 2], c[mi][ni][half * 2 + 1]);
                if (nt < 64) {
                    int col = nt * 128 + colL;
                    bool isQ = col < HDTOT;
                    float* o = isQ ? q : k;
                    int nn = isQ ? col : col - HDTOT;
                    *(float2*)&o[(size_t)s * HDTOT + nn] = fv;
                } else {
                    int cy = (nt - 64) * 128 + colL;
                    float* o = (cy < HD) ? yq : yk;
                    int nn = (cy < HD) ? cy : cy - HD;
                    *(float2*)&o[(size_t)s * HD + nn] = fv;
                }
            }
        }
    }
}

// ---------------- K5s: scores GEMM ----------------
__global__ void __launch_bounds__(256) k_scores(
    const __nv_bfloat16* __restrict__ Qs, const __nv_bfloat16* __restrict__ Ks,
    float* __restrict__ S)
{
    extern __shared__ char sm[];
    uint32_t smb = smem_u32(sm);
    int t = threadIdx.x, w = t >> 5, lane = t & 31;
    int wm = w >> 2, wn = w & 3;
    int m0 = blockIdx.x * 128, n0 = blockIdx.y * 128, z = blockIdx.z;

    const __nv_bfloat16* Ab = Qs + (size_t)z * SP * KH + (size_t)m0 * KH;
    const __nv_bfloat16* Bb = Ks + (size_t)z * SP * KH + (size_t)n0 * KH;

    float c[4][4][4];
    #pragma unroll
    for (int i = 0; i < 4; i++)
        #pragma unroll
        for (int j = 0; j < 4; j++)
            #pragma unroll
            for (int e = 0; e < 4; e++) c[i][j][e] = 0.f;

    mma_mainloop(smb, Ab, Bb, KH, KH, KH / 64, t, lane, wm, wn, c);

    int r0 = lane >> 2, c0 = (lane & 3) * 2;
    #pragma unroll
    for (int mi = 0; mi < 4; mi++) {
        #pragma unroll
        for (int ni = 0; ni < 4; ni++) {
            #pragma unroll
            for (int half = 0; half < 2; half++) {
                int row = m0 + wm * 64 + mi * 16 + r0 + half * 8;
                int col = n0 + wn * 32 + ni * 8 + c0;
                float2 fv = make_float2(c[mi][ni][half * 2], c[mi][ni][half * 2 + 1]);
                *(float2*)&S[((size_t)(z * SP + row)) * SP + col] = fv;
            }
        }
    }
}

// ---------------- K5b: coalesced split of q/k -> Qs/Ks ----------------
__global__ void k_splitqk(const float* __restrict__ q, const float* __restrict__ k,
                          __nv_bfloat16* __restrict__ Qs, __nv_bfloat16* __restrict__ Ks) {
    int idx = blockIdx.x * 256 + threadIdx.x;
    int s = idx >> 12, n = idx & 4095;
    int h = n >> 7, c = n & 127;
    size_t base = ((size_t)h * SP + s) * KH + c;
    __nv_bfloat16 hi, lo;
    split2(q[idx], hi, lo);
    Qs[base] = hi; Qs[base + 128] = lo; Qs[base + 256] = hi;
    split2(k[idx], hi, lo);
    Ks[base] = hi; Ks[base + 128] = hi; Ks[base + 256] = lo;
}

// ---------------- K6: suffix tables ----------------
__global__ void __launch_bounds__(256) k_suffix(const float* __restrict__ qk,
                                                const float* __restrict__ rbias,
                                                const float* __restrict__ W_pos,
                                                const float* __restrict__ b_pos,
                                                float* __restrict__ T) {
    extern __shared__ float smf[];
    float* ws = smf;
    float* qs = ws + 65 * 132;
    float* Ms = qs + 32 * 132;
    int h = blockIdx.y;
    int q0 = blockIdx.x * 32;
    int t = threadIdx.x;
    for (int i = t; i < 65 * 128; i += 256) {
        int f = i >> 7, c = i & 127;
        ws[f * 132 + c] = (f < 64) ? W_pos[f * HDTOT + h * HD + c] : b_pos[h * HD + c];
    }
    for (int i = t; i < 32 * 128; i += 256) {
        int r = i >> 7, c = i & 127;
        qs[r * 132 + c] = qk[(size_t)(q0 + r) * HDTOT + h * HD + c] + rbias[h * HD + c];
    }
    __syncthreads();
    for (int i = t; i < 32 * 65; i += 256) {
        int r = i / 65, f = i % 65;
        const float4* qr = (const float4*)&qs[r * 132];
        const float4* wr = (const float4*)&ws[f * 132];
        float acc = 0.f;
        #pragma unroll
        for (int c4 = 0; c4 < 32; c4++) {
            float4 a = qr[c4], b = wr[c4];
            acc += a.x * b.x + a.y * b.y + a.z * b.z + a.w * b.w;
        }
        Ms[r * 65 + f] = acc;
    }
    __syncthreads();
    for (int i = t; i < 32 * 33; i += 256) {
        int r = i / 33, j = i % 33;
        float sa = Ms[r * 65 + 64];
        float sb = 0.f;
        for (int f = j; f < 32; f++) { sa += Ms[r * 65 + f]; sb += Ms[r * 65 + 32 + f]; }
        int q = q0 + r;
        T[((j * SP + q) * NH + h) * 2] = sa;
        T[((j * SP + q) * NH + h) * 2 + 1] = sb;
    }
}

// ---------------- K7: fold suffix tables through W_pair ----------------
__global__ void __launch_bounds__(128) k_fold(const float* __restrict__ TQ,
                                              const float* __restrict__ TK,
                                              const float* __restrict__ Wp,
                                              float* __restrict__ RQ,
                                              float* __restrict__ RK) {
    __shared__ float tq[33 * 64], tk[33 * 64];
    int q = blockIdx.x, t = threadIdx.x;
    for (int i = t; i < 33 * 64; i += 128) {
        int j = i >> 6, r = i & 63;
        tq[i] = TQ[((size_t)j * SP + q) * 64 + r];
        tk[i] = TK[((size_t)j * SP + q) * 64 + r];
    }
    float wcol[NH];
    #pragma unroll
    for (int h = 0; h < NH; h++) wcol[h] = Wp[h * HD + t];
    __syncthreads();
    for (int j = 0; j < 33; j++) {
        float aa = 0.f, ab = 0.f, ba = 0.f, bb = 0.f;
        const float* tqj = &tq[j * 64];
        const float* tkj = &tk[j * 64];
        #pragma unroll
        for (int h = 0; h < NH; h++) {
            float w = wcol[h];
            aa += tqj[2 * h] * w;  ab += tqj[2 * h + 1] * w;
            ba += tkj[2 * h] * w;  bb += tkj[2 * h + 1] * w;
        }
        size_t ob = ((size_t)j * SP + q) * 256 + t * 2;
        RQ[ob] = aa; RQ[ob + 1] = ab;
        RK[ob] = ba; RK[ob + 1] = bb;
    }
}

// ---------------- K8: final pass (FFMA) ----------------
__global__ void __launch_bounds__(256) k_pair2(const float* __restrict__ S,
                                               const float* __restrict__ RQ,
                                               const float* __restrict__ RK,
                                               const int* __restrict__ f0tab,
                                               const float* __restrict__ Wp,
                                               const float* __restrict__ bp,
                                               const float* __restrict__ yq,
                                               const float* __restrict__ yk,
                                               float* __restrict__ out) {
    __shared__ float Sh[128 * 36];
    int t = threadIdx.x;
    int q = blockIdx.x, k0 = blockIdx.y * 128;
    for (int i = t; i < 4096; i += 256) {
        int h = i >> 7, kk = i & 127;
        Sh[kk * 36 + h] = S[(((size_t)h * SP + q) << 9) + k0 + kk];
    }
    int d = t & 127, g = t >> 7;
    float wcol[NH];
    #pragma unroll
    for (int h = 0; h < NH; h++) wcol[h] = Wp[h * HD + d];
    float base0 = bp[d] + yq[q * HD + d];
    __syncthreads();
    for (int kk = g * 64; kk < g * 64 + 64; kk++) {
        int k = k0 + kk;
        int delta = k - q;
        int dd = delta >= 0 ? delta : -delta;
        float sgn = delta > 0 ? 1.f : (delta < 0 ? -1.f : 0.f);
        int j = f0tab[dd];
        float2 rq = *(const float2*)&RQ[((size_t)j * SP + q) * 256 + d * 2];
        float2 rk = *(const float2*)&RK[((size_t)j * SP + k) * 256 + d * 2];
        float acc = base0 + yk[k * HD + d]
                  + 0.5f * (rq.x + rk.x) + 0.5f * sgn * (rq.y - rk.y);
        const float* sr = &Sh[kk * 36];
        #pragma unroll
        for (int h4 = 0; h4 < 8; h4++) {
            float4 sv = *(const float4*)&sr[h4 * 4];
            acc += sv.x * wcol[h4 * 4] + sv.y * wcol[h4 * 4 + 1] +
                   sv.z * wcol[h4 * 4 + 2] + sv.w * wcol[h4 * 4 + 3];
        }
        out[((size_t)(q * SP + k)) * HD + d] = acc;
    }
}

// ---------------- launcher ----------------
#define SUF_SMEM ((65 * 132 + 32 * 132 + 32 * 65) * 4)

extern "C" void kernel_launch(void* const* d_in, const int* in_sizes, int n_in,
                              void* d_out, int out_size) {
    const float* x      = (const float*)d_in[0];
    const float* w_rms  = (const float*)d_in[1];
    const float* W_q    = (const float*)d_in[2];
    const float* W_k    = (const float*)d_in[3];
    const float* W_pos  = (const float*)d_in[4];
    const float* b_pos  = (const float*)d_in[5];
    const float* qrb    = (const float*)d_in[6];
    const float* krb    = (const float*)d_in[7];
    const float* W_yq   = (const float*)d_in[8];
    const float* W_yk   = (const float*)d_in[9];
    const float* W_pair = (const float*)d_in[10];
    const float* b_pair = (const float*)d_in[11];
    float* out = (float*)d_out;

    float *qb, *kb, *yq, *yk, *TQ, *TK, *RQ, *RK, *Sb;
    __nv_bfloat16 *Xn, *Xg, *Ww, *Wy, *Qs, *Ks;
    int* f0;
    cudaGetSymbolAddress((void**)&qb, g_q);
    cudaGetSymbolAddress((void**)&kb, g_k);
    cudaGetSymbolAddress((void**)&yq, g_yq);
    cudaGetSymbolAddress((void**)&yk, g_yk);
    cudaGetSymbolAddress((void**)&TQ, g_TQ);
    cudaGetSymbolAddress((void**)&TK, g_TK);
    cudaGetSymbolAddress((void**)&RQ, g_RQ);
    cudaGetSymbolAddress((void**)&RK, g_RK);
    cudaGetSymbolAddress((void**)&Sb, g_S);
    cudaGetSymbolAddress((void**)&Xn, g_Xn);
    cudaGetSymbolAddress((void**)&Xg, g_Xg);
    cudaGetSymbolAddress((void**)&Ww, g_Ww);
    cudaGetSymbolAddress((void**)&Wy, g_Wy);
    cudaGetSymbolAddress((void**)&Qs, g_Qs);
    cudaGetSymbolAddress((void**)&Ks, g_Ks);
    cudaGetSymbolAddress((void**)&f0, g_f0);

    cudaFuncSetAttribute(k_proj, cudaFuncAttributeMaxDynamicSharedMemorySize, MMA_SMEM);
    cudaFuncSetAttribute(k_scores, cudaFuncAttributeMaxDynamicSharedMemorySize, MMA_SMEM);
    cudaFuncSetAttribute(k_suffix, cudaFuncAttributeMaxDynamicSharedMemorySize, SUF_SMEM);

    k_pool<<<SP, 256>>>(x, w_rms, Xn, Xg);                                  // idx 0
    k_wsplit<<<dim3(2 * HD / 32, DIN / 32), 256>>>(W_yq, W_yk, HD, Wy);     // idx 1
    k_wsplit<<<dim3(2 * HDTOT / 32, DIN / 32), 256>>>(W_q, W_k, HDTOT, Ww); // idx 2
    k_proj<<<264, 256, MMA_SMEM>>>(Xn, Xg, Ww, Wy, qb, kb, yq, yk);         // idx 3 (profiled)
    k_f0<<<1, 512>>>(f0);                                                   // idx 4

    k_splitqk<<<SP * HDTOT / 256, 256>>>(qb, kb, Qs, Ks);

    dim3 gs(SP / 32, NH);
    k_suffix<<<gs, 256, SUF_SMEM>>>(qb, qrb, W_pos, b_pos, TQ);
    k_suffix<<<gs, 256, SUF_SMEM>>>(kb, krb, W_pos, b_pos, TK);
    k_fold<<<SP, 128>>>(TQ, TK, W_pair, RQ, RK);

    k_scores<<<dim3(4, 4, NH), 256, MMA_SMEM>>>(Qs, Ks, Sb);

    k_pair2<<<dim3(SP, 4), 256>>>(Sb, RQ, RK, f0, W_pair, b_pair, yq, yk, out);
}

// round 8
// speedup vs baseline: 2.4997x; 1.0073x over previous
#include <cuda_runtime.h>
#include <cuda_bf16.h>
#include <math.h>
#include <stdint.h>

#define SP    512
#define DIN   1536
#define NH    32
#define HD    128
#define HDTOT 4096
#define K3    4608   // 3*DIN
#define KH    384    // 3*HD

// ---------------- scratch ----------------
__device__ __nv_bfloat16 g_Xn[SP*K3];
__device__ __nv_bfloat16 g_Xg[SP*K3];
__device__ __nv_bfloat16 g_Ww[(size_t)2*HDTOT*K3];
__device__ __nv_bfloat16 g_Wy[2*HD*K3];
__device__ float g_q[SP*HDTOT];
__device__ float g_k[SP*HDTOT];
__device__ float g_yq[SP*HD];
__device__ float g_yk[SP*HD];
__device__ __nv_bfloat16 g_Qs[(size_t)NH*SP*KH];
__device__ __nv_bfloat16 g_Ks[(size_t)NH*SP*KH];
__device__ float g_S[(size_t)NH*SP*SP];
__device__ float g_TQ[33*SP*NH*2];
__device__ float g_TK[33*SP*NH*2];
__device__ float g_RQ[33*SP*HD*2];
__device__ float g_RK[33*SP*HD*2];
__device__ int   g_f0[SP];

// ---------------- helpers ----------------
__device__ __forceinline__ uint32_t smem_u32(const void* p) {
    uint32_t a;
    asm("{ .reg .u64 t; cvta.to.shared.u64 t, %1; cvt.u32.u64 %0, t; }" : "=r"(a) : "l"(p));
    return a;
}
__device__ __forceinline__ void cp16(uint32_t dst, const void* src) {
    asm volatile("cp.async.cg.shared.global [%0], [%1], 16;" :: "r"(dst), "l"(src));
}
#define CP_COMMIT() asm volatile("cp.async.commit_group;" ::: "memory")
#define CP_WAIT1()  asm volatile("cp.async.wait_group 1;" ::: "memory")

__device__ __forceinline__ void ldm_x4(uint32_t* r, uint32_t addr) {
    asm volatile("ldmatrix.sync.aligned.m8n8.x4.shared.b16 {%0,%1,%2,%3}, [%4];"
                 : "=r"(r[0]), "=r"(r[1]), "=r"(r[2]), "=r"(r[3]) : "r"(addr));
}
__device__ __forceinline__ void mma16816(float* c, const uint32_t* a, uint32_t b0, uint32_t b1) {
    asm volatile("mma.sync.aligned.m16n8k16.row.col.f32.bf16.bf16.f32 "
                 "{%0,%1,%2,%3}, {%4,%5,%6,%7}, {%8,%9}, {%0,%1,%2,%3};"
                 : "+f"(c[0]), "+f"(c[1]), "+f"(c[2]), "+f"(c[3])
                 : "r"(a[0]), "r"(a[1]), "r"(a[2]), "r"(a[3]), "r"(b0), "r"(b1));
}
__device__ __forceinline__ void split2(float v, __nv_bfloat16& hi, __nv_bfloat16& lo) {
    hi = __float2bfloat16(v);
    lo = __float2bfloat16(v - __bfloat162float(hi));
}

// BK=64: A tile 128x72 bf16 (144 B/row), B tile 256x72 bf16
#define A_TILE 18432                  // 128*144
#define B_TILE 36864                  // 256*144
#define STAGE_BYTES (A_TILE + B_TILE) // 55296
#define MMA_SMEM (3 * STAGE_BYTES)    // 165888

// mainloop: CTA 128x256 tile, 8 warps as 2(m) x 4(n), warp 64x64, K=niter*64
__device__ __forceinline__ void mma_mainloop(
    uint32_t smb, const __nv_bfloat16* __restrict__ Ab,
    const __nv_bfloat16* __restrict__ Bb, int sA, int sB, int niter,
    int t, int lane, int wm, int wn, float c[4][8][4])
{
    uint32_t aoff[4], boff[4];
    {
        int lr = lane & 15, lc = lane >> 4;
        #pragma unroll
        for (int mi = 0; mi < 4; mi++) aoff[mi] = (wm * 64 + mi * 16 + lr) * 144 + lc * 16;
        #pragma unroll
        for (int nj = 0; nj < 4; nj++) boff[nj] = A_TILE + (wn * 64 + nj * 16 + lr) * 144 + lc * 16;
    }
    int lrow = t >> 3;            // 0..31
    int lc16 = (t & 7) * 16;      // byte col
    int lcol_el = (t & 7) * 8;    // element col

    // prologue: stages 0,1
    #pragma unroll
    for (int s = 0; s < 2; s++) {
        uint32_t db = smb + s * STAGE_BYTES;
        #pragma unroll
        for (int i = 0; i < 4; i++) {
            int row = lrow + i * 32;
            cp16(db + row * 144 + lc16, Ab + (size_t)row * sA + s * 64 + lcol_el);
        }
        #pragma unroll
        for (int i = 0; i < 8; i++) {
            int row = lrow + i * 32;
            cp16(db + A_TILE + row * 144 + lc16, Bb + (size_t)row * sB + s * 64 + lcol_el);
        }
        CP_COMMIT();
    }

    for (int ck = 0; ck < niter; ck++) {
        CP_WAIT1();
        __syncthreads();
        int pf = ck + 2;
        if (pf < niter) {
            uint32_t db = smb + (pf % 3) * STAGE_BYTES;
            #pragma unroll
            for (int i = 0; i < 4; i++) {
                int row = lrow + i * 32;
                cp16(db + row * 144 + lc16, Ab + (size_t)row * sA + pf * 64 + lcol_el);
            }
            #pragma unroll
            for (int i = 0; i < 8; i++) {
                int row = lrow + i * 32;
                cp16(db + A_TILE + row * 144 + lc16, Bb + (size_t)row * sB + pf * 64 + lcol_el);
            }
        }
        CP_COMMIT();
        uint32_t sa = smb + (ck % 3) * STAGE_BYTES;
        #pragma unroll
        for (int kk = 0; kk < 4; kk++) {
            uint32_t a[4][4], b[4][4];
            #pragma unroll
            for (int mi = 0; mi < 4; mi++) ldm_x4(a[mi], sa + aoff[mi] + kk * 32);
            #pragma unroll
            for (int nj = 0; nj < 4; nj++) ldm_x4(b[nj], sa + boff[nj] + kk * 32);
            #pragma unroll
            for (int mi = 0; mi < 4; mi++)
                #pragma unroll
                for (int ni = 0; ni < 8; ni++)
                    mma16816(c[mi][ni], a[mi], b[ni >> 1][ni & 1], b[ni >> 1][(ni & 1) + 2]);
        }
    }
}

// ---------------- K1: pool + rmsnorm + gelu -> bf16 splits ----------------
__global__ void k_pool(const float* __restrict__ x, const float* __restrict__ w_rms,
                       __nv_bfloat16* __restrict__ Xn, __nv_bfloat16* __restrict__ Xg) {
    int sp = blockIdx.x;
    const float* xb = x + (size_t)sp * 16 * DIN;
    __shared__ float xp[DIN];
    __shared__ float red[256];
    int t = threadIdx.x;
    float ssq = 0.f;
    for (int c = t; c < DIN; c += 256) {
        float s = 0.f;
        #pragma unroll
        for (int r = 0; r < 16; r++) s += xb[r * DIN + c];
        s *= (1.f / 16.f);
        xp[c] = s;
        ssq += s * s;
    }
    red[t] = ssq;
    __syncthreads();
    for (int o = 128; o > 0; o >>= 1) {
        if (t < o) red[t] += red[t + o];
        __syncthreads();
    }
    float scale = rsqrtf(red[0] / (float)DIN + 1e-6f);
    size_t b = (size_t)sp * K3;
    for (int c = t; c < DIN; c += 256) {
        float v = xp[c] * scale * w_rms[c];
        __nv_bfloat16 hi, lo;
        split2(v, hi, lo);
        Xn[b + c] = hi; Xn[b + DIN + c] = hi; Xn[b + 2 * DIN + c] = lo;
        float g = v * normcdff(v);
        split2(g, hi, lo);
        Xg[b + c] = hi; Xg[b + DIN + c] = hi; Xg[b + 2 * DIN + c] = lo;
    }
}

// ---------------- K2: f0 table ----------------
__global__ void k_f0(int* __restrict__ f0) {
    int d = threadIdx.x;
    if (d < SP) {
        const float log_step = (float)(log(481.0) / 32.0);
        int cnt = 0;
        #pragma unroll
        for (int f = 0; f < 32; f++) {
            float cw = (float)f + expf((float)f * log_step);
            if (cw <= (float)d) cnt++;
        }
        f0[d] = cnt;
    }
}

// ---------------- K4: transpose + split weights [hi,lo,hi] ----------------
__global__ void k_wsplit(const float* __restrict__ srcA, const float* __restrict__ srcB,
                         int Nsrc, __nv_bfloat16* __restrict__ dst) {
    __shared__ float tile[32][33];
    int t = threadIdx.x;
    int n0 = blockIdx.x * 32, k0 = blockIdx.y * 32;
    const float* src = (n0 < Nsrc) ? srcA : srcB;
    int nb = (n0 < Nsrc) ? n0 : (n0 - Nsrc);
    #pragma unroll
    for (int i = 0; i < 4; i++) {
        int r = (t >> 5) + i * 8, c = t & 31;
        tile[r][c] = src[(size_t)(k0 + r) * Nsrc + nb + c];
    }
    __syncthreads();
    #pragma unroll
    for (int i = 0; i < 4; i++) {
        int rn = (t >> 5) + i * 8;
        int kk = k0 + (t & 31);
        float v = tile[t & 31][rn];
        __nv_bfloat16 hi, lo;
        split2(v, hi, lo);
        size_t row = (size_t)(n0 + rn) * K3;
        dst[row + kk] = hi;
        dst[row + DIN + kk] = lo;
        dst[row + 2 * DIN + kk] = hi;
    }
}

// ---------------- K5: fused projection GEMM (CTA 128x256) ----------------
// blocks 0..127: qk (mt=bid&3, nt=bid>>2, N-tile of 256 within 8192)
// blocks 128..131: y (mt=bid-128, single 256-wide N tile of Wy)
__global__ void __launch_bounds__(256) k_proj(
    const __nv_bfloat16* __restrict__ Xn, const __nv_bfloat16* __restrict__ Xg,
    const __nv_bfloat16* __restrict__ Ww, const __nv_bfloat16* __restrict__ Wy,
    float* __restrict__ q, float* __restrict__ k,
    float* __restrict__ yq, float* __restrict__ yk)
{
    extern __shared__ char sm[];
    uint32_t smb = smem_u32(sm);
    int t = threadIdx.x, w = t >> 5, lane = t & 31;
    int wm = w >> 2, wn = w & 3;
    int bid = blockIdx.x;
    int mt, nt;
    if (bid < 128) { mt = bid & 3; nt = bid >> 2; }
    else { mt = bid - 128; nt = 32; }

    const __nv_bfloat16* Ab = (bid < 128) ? (Xn + (size_t)mt * 128 * K3)
                                          : (Xg + (size_t)mt * 128 * K3);
    const __nv_bfloat16* Bb = (nt < 32) ? (Ww + (size_t)nt * 256 * K3) : Wy;

    float c[4][8][4];
    #pragma unroll
    for (int i = 0; i < 4; i++)
        #pragma unroll
        for (int j = 0; j < 8; j++)
            #pragma unroll
            for (int e = 0; e < 4; e++) c[i][j][e] = 0.f;

    mma_mainloop(smb, Ab, Bb, K3, K3, K3 / 64, t, lane, wm, wn, c);

    int r0 = lane >> 2, c0 = (lane & 3) * 2;
    int srow0 = mt * 128;
    #pragma unroll
    for (int mi = 0; mi < 4; mi++) {
        #pragma unroll
        for (int ni = 0; ni < 8; ni++) {
            #pragma unroll
            for (int half = 0; half < 2; half++) {
                int s = srow0 + wm * 64 + mi * 16 + r0 + half * 8;
                int colL = wn * 64 + ni * 8 + c0;   // 0..255
                float2 fv = make_float2(c[mi][ni][half * 2], c[mi][ni][half * 2 + 1]);
                if (nt < 32) {
                    int col = nt * 256 + colL;
                    bool isQ = col < HDTOT;
                    float* o = isQ ? q : k;
                    int nn = isQ ? col : col - HDTOT;
                    *(float2*)&o[(size_t)s * HDTOT + nn] = fv;
                } else {
                    float* o = (colL < HD) ? yq : yk;
                    int nn = (colL < HD) ? colL : colL - HD;
                    *(float2*)&o[(size_t)s * HD + nn] = fv;
                }
            }
        }
    }
}

// ---------------- K5s: scores GEMM (CTA 128x256, batched over heads) ----------------
__global__ void __launch_bounds__(256) k_scores(
    const __nv_bfloat16* __restrict__ Qs, const __nv_bfloat16* __restrict__ Ks,
    float* __restrict__ S)
{
    extern __shared__ char sm[];
    uint32_t smb = smem_u32(sm);
    int t = threadIdx.x, w = t >> 5, lane = t & 31;
    int wm = w >> 2, wn = w & 3;
    int m0 = blockIdx.x * 128, n0 = blockIdx.y * 256, z = blockIdx.z;

    const __nv_bfloat16* Ab = Qs + (size_t)z * SP * KH + (size_t)m0 * KH;
    const __nv_bfloat16* Bb = Ks + (size_t)z * SP * KH + (size_t)n0 * KH;

    float c[4][8][4];
    #pragma unroll
    for (int i = 0; i < 4; i++)
        #pragma unroll
        for (int j = 0; j < 8; j++)
            #pragma unroll
            for (int e = 0; e < 4; e++) c[i][j][e] = 0.f;

    mma_mainloop(smb, Ab, Bb, KH, KH, KH / 64, t, lane, wm, wn, c);

    int r0 = lane >> 2, c0 = (lane & 3) * 2;
    #pragma unroll
    for (int mi = 0; mi < 4; mi++) {
        #pragma unroll
        for (int ni = 0; ni < 8; ni++) {
            #pragma unroll
            for (int half = 0; half < 2; half++) {
                int row = m0 + wm * 64 + mi * 16 + r0 + half * 8;
                int col = n0 + wn * 64 + ni * 8 + c0;
                float2 fv = make_float2(c[mi][ni][half * 2], c[mi][ni][half * 2 + 1]);
                *(float2*)&S[((size_t)(z * SP + row)) * SP + col] = fv;
            }
        }
    }
}

// ---------------- K5b: coalesced split of q/k -> Qs/Ks ----------------
__global__ void k_splitqk(const float* __restrict__ q, const float* __restrict__ k,
                          __nv_bfloat16* __restrict__ Qs, __nv_bfloat16* __restrict__ Ks) {
    int idx = blockIdx.x * 256 + threadIdx.x;
    int s = idx >> 12, n = idx & 4095;
    int h = n >> 7, c = n & 127;
    size_t base = ((size_t)h * SP + s) * KH + c;
    __nv_bfloat16 hi, lo;
    split2(q[idx], hi, lo);
    Qs[base] = hi; Qs[base + 128] = lo; Qs[base + 256] = hi;
    split2(k[idx], hi, lo);
    Ks[base] = hi; Ks[base + 128] = hi; Ks[base + 256] = lo;
}

// ---------------- K6: suffix tables ----------------
__global__ void __launch_bounds__(256) k_suffix(const float* __restrict__ qk,
                                                const float* __restrict__ rbias,
                                                const float* __restrict__ W_pos,
                                                const float* __restrict__ b_pos,
                                                float* __restrict__ T) {
    extern __shared__ float smf[];
    float* ws = smf;
    float* qs = ws + 65 * 132;
    float* Ms = qs + 32 * 132;
    int h = blockIdx.y;
    int q0 = blockIdx.x * 32;
    int t = threadIdx.x;
    for (int i = t; i < 65 * 128; i += 256) {
        int f = i >> 7, c = i & 127;
        ws[f * 132 + c] = (f < 64) ? W_pos[f * HDTOT + h * HD + c] : b_pos[h * HD + c];
    }
    for (int i = t; i < 32 * 128; i += 256) {
        int r = i >> 7, c = i & 127;
        qs[r * 132 + c] = qk[(size_t)(q0 + r) * HDTOT + h * HD + c] + rbias[h * HD + c];
    }
    __syncthreads();
    for (int i = t; i < 32 * 65; i += 256) {
        int r = i / 65, f = i % 65;
        const float4* qr = (const float4*)&qs[r * 132];
        const float4* wr = (const float4*)&ws[f * 132];
        float acc = 0.f;
        #pragma unroll
        for (int c4 = 0; c4 < 32; c4++) {
            float4 a = qr[c4], b = wr[c4];
            acc += a.x * b.x + a.y * b.y + a.z * b.z + a.w * b.w;
        }
        Ms[r * 65 + f] = acc;
    }
    __syncthreads();
    for (int i = t; i < 32 * 33; i += 256) {
        int r = i / 33, j = i % 33;
        float sa = Ms[r * 65 + 64];
        float sb = 0.f;
        for (int f = j; f < 32; f++) { sa += Ms[r * 65 + f]; sb += Ms[r * 65 + 32 + f]; }
        int q = q0 + r;
        T[((j * SP + q) * NH + h) * 2] = sa;
        T[((j * SP + q) * NH + h) * 2 + 1] = sb;
    }
}

// ---------------- K7: fold suffix tables through W_pair ----------------
__global__ void __launch_bounds__(128) k_fold(const float* __restrict__ TQ,
                                              const float* __restrict__ TK,
                                              const float* __restrict__ Wp,
                                              float* __restrict__ RQ,
                                              float* __restrict__ RK) {
    __shared__ float tq[33 * 64], tk[33 * 64];
    int q = blockIdx.x, t = threadIdx.x;
    for (int i = t; i < 33 * 64; i += 128) {
        int j = i >> 6, r = i & 63;
        tq[i] = TQ[((size_t)j * SP + q) * 64 + r];
        tk[i] = TK[((size_t)j * SP + q) * 64 + r];
    }
    float wcol[NH];
    #pragma unroll
    for (int h = 0; h < NH; h++) wcol[h] = Wp[h * HD + t];
    __syncthreads();
    for (int j = 0; j < 33; j++) {
        float aa = 0.f, ab = 0.f, ba = 0.f, bb = 0.f;
        const float* tqj = &tq[j * 64];
        const float* tkj = &tk[j * 64];
        #pragma unroll
        for (int h = 0; h < NH; h++) {
            float w = wcol[h];
            aa += tqj[2 * h] * w;  ab += tqj[2 * h + 1] * w;
            ba += tkj[2 * h] * w;  bb += tkj[2 * h + 1] * w;
        }
        size_t ob = ((size_t)j * SP + q) * 256 + t * 2;
        RQ[ob] = aa; RQ[ob + 1] = ab;
        RK[ob] = ba; RK[ob + 1] = bb;
    }
}

// ---------------- K8: final pass (FFMA) ----------------
__global__ void __launch_bounds__(256) k_pair2(const float* __restrict__ S,
                                               const float* __restrict__ RQ,
                                               const float* __restrict__ RK,
                                               const int* __restrict__ f0tab,
                                               const float* __restrict__ Wp,
                                               const float* __restrict__ bp,
                                               const float* __restrict__ yq,
                                               const float* __restrict__ yk,
                                               float* __restrict__ out) {
    __shared__ float Sh[128 * 36];
    int t = threadIdx.x;
    int q = blockIdx.x, k0 = blockIdx.y * 128;
    for (int i = t; i < 4096; i += 256) {
        int h = i >> 7, kk = i & 127;
        Sh[kk * 36 + h] = S[(((size_t)h * SP + q) << 9) + k0 + kk];
    }
    int d = t & 127, g = t >> 7;
    float wcol[NH];
    #pragma unroll
    for (int h = 0; h < NH; h++) wcol[h] = Wp[h * HD + d];
    float base0 = bp[d] + yq[q * HD + d];
    __syncthreads();
    for (int kk = g * 64; kk < g * 64 + 64; kk++) {
        int k = k0 + kk;
        int delta = k - q;
        int dd = delta >= 0 ? delta : -delta;
        float sgn = delta > 0 ? 1.f : (delta < 0 ? -1.f : 0.f);
        int j = f0tab[dd];
        float2 rq = *(const float2*)&RQ[((size_t)j * SP + q) * 256 + d * 2];
        float2 rk = *(const float2*)&RK[((size_t)j * SP + k) * 256 + d * 2];
        float acc = base0 + yk[k * HD + d]
                  + 0.5f * (rq.x + rk.x) + 0.5f * sgn * (rq.y - rk.y);
        const float* sr = &Sh[kk * 36];
        #pragma unroll
        for (int h4 = 0; h4 < 8; h4++) {
            float4 sv = *(const float4*)&sr[h4 * 4];
            acc += sv.x * wcol[h4 * 4] + sv.y * wcol[h4 * 4 + 1] +
                   sv.z * wcol[h4 * 4 + 2] + sv.w * wcol[h4 * 4 + 3];
        }
        out[((size_t)(q * SP + k)) * HD + d] = acc;
    }
}

// ---------------- launcher ----------------
#define SUF_SMEM ((65 * 132 + 32 * 132 + 32 * 65) * 4)

extern "C" void kernel_launch(void* const* d_in, const int* in_sizes, int n_in,
                              void* d_out, int out_size) {
    const float* x      = (const float*)d_in[0];
    const float* w_rms  = (const float*)d_in[1];
    const float* W_q    = (const float*)d_in[2];
    const float* W_k    = (const float*)d_in[3];
    const float* W_pos  = (const float*)d_in[4];
    const float* b_pos  = (const float*)d_in[5];
    const float* qrb    = (const float*)d_in[6];
    const float* krb    = (const float*)d_in[7];
    const float* W_yq   = (const float*)d_in[8];
    const float* W_yk   = (const float*)d_in[9];
    const float* W_pair = (const float*)d_in[10];
    const float* b_pair = (const float*)d_in[11];
    float* out = (float*)d_out;

    float *qb, *kb, *yq, *yk, *TQ, *TK, *RQ, *RK, *Sb;
    __nv_bfloat16 *Xn, *Xg, *Ww, *Wy, *Qs, *Ks;
    int* f0;
    cudaGetSymbolAddress((void**)&qb, g_q);
    cudaGetSymbolAddress((void**)&kb, g_k);
    cudaGetSymbolAddress((void**)&yq, g_yq);
    cudaGetSymbolAddress((void**)&yk, g_yk);
    cudaGetSymbolAddress((void**)&TQ, g_TQ);
    cudaGetSymbolAddress((void**)&TK, g_TK);
    cudaGetSymbolAddress((void**)&RQ, g_RQ);
    cudaGetSymbolAddress((void**)&RK, g_RK);
    cudaGetSymbolAddress((void**)&Sb, g_S);
    cudaGetSymbolAddress((void**)&Xn, g_Xn);
    cudaGetSymbolAddress((void**)&Xg, g_Xg);
    cudaGetSymbolAddress((void**)&Ww, g_Ww);
    cudaGetSymbolAddress((void**)&Wy, g_Wy);
    cudaGetSymbolAddress((void**)&Qs, g_Qs);
    cudaGetSymbolAddress((void**)&Ks, g_Ks);
    cudaGetSymbolAddress((void**)&f0, g_f0);

    cudaFuncSetAttribute(k_proj, cudaFuncAttributeMaxDynamicSharedMemorySize, MMA_SMEM);
    cudaFuncSetAttribute(k_scores, cudaFuncAttributeMaxDynamicSharedMemorySize, MMA_SMEM);
    cudaFuncSetAttribute(k_suffix, cudaFuncAttributeMaxDynamicSharedMemorySize, SUF_SMEM);

    k_pool<<<SP, 256>>>(x, w_rms, Xn, Xg);                                  // idx 0
    k_wsplit<<<dim3(2 * HD / 32, DIN / 32), 256>>>(W_yq, W_yk, HD, Wy);     // idx 1
    k_wsplit<<<dim3(2 * HDTOT / 32, DIN / 32), 256>>>(W_q, W_k, HDTOT, Ww); // idx 2
    k_proj<<<132, 256, MMA_SMEM>>>(Xn, Xg, Ww, Wy, qb, kb, yq, yk);         // idx 3 (profiled)
    k_f0<<<1, 512>>>(f0);                                                   // idx 4

    k_splitqk<<<SP * HDTOT / 256, 256>>>(qb, kb, Qs, Ks);

    dim3 gs(SP / 32, NH);
    k_suffix<<<gs, 256, SUF_SMEM>>>(qb, qrb, W_pos, b_pos, TQ);
    k_suffix<<<gs, 256, SUF_SMEM>>>(kb, krb, W_pos, b_pos, TK);
    k_fold<<<SP, 128>>>(TQ, TK, W_pair, RQ, RK);

    k_scores<<<dim3(4, 2, NH), 256, MMA_SMEM>>>(Qs, Ks, Sb);

    k_pair2<<<dim3(SP, 4), 256>>>(Sb, RQ, RK, f0, W_pair, b_pair, yq, yk, out);
}

// round 9
// speedup vs baseline: 2.5018x; 1.0008x over previous
#include <cuda_runtime.h>
#include <cuda_bf16.h>
#include <math.h>
#include <stdint.h>

#define SP    512
#define DIN   1536
#define NH    32
#define HD    128
#define HDTOT 4096
#define K3    4608   // 3*DIN
#define KH    384    // 3*HD

// ---------------- scratch ----------------
__device__ __nv_bfloat16 g_Xn[SP*K3];
__device__ __nv_bfloat16 g_Xg[SP*K3];
__device__ __nv_bfloat16 g_Ww[(size_t)2*HDTOT*K3];
__device__ __nv_bfloat16 g_Wy[2*HD*K3];
__device__ float g_q[SP*HDTOT];
__device__ float g_k[SP*HDTOT];
__device__ float g_yq[SP*HD];
__device__ float g_yk[SP*HD];
__device__ __nv_bfloat16 g_Qs[(size_t)NH*SP*KH];
__device__ __nv_bfloat16 g_Ks[(size_t)NH*SP*KH];
__device__ float g_S[(size_t)NH*SP*SP];
__device__ float g_TQ[33*SP*NH*2];
__device__ float g_TK[33*SP*NH*2];
__device__ float g_RQ[33*SP*HD*2];
__device__ float g_RK[33*SP*HD*2];
__device__ int   g_f0[SP];

// ---------------- helpers ----------------
__device__ __forceinline__ uint32_t smem_u32(const void* p) {
    uint32_t a;
    asm("{ .reg .u64 t; cvta.to.shared.u64 t, %1; cvt.u32.u64 %0, t; }" : "=r"(a) : "l"(p));
    return a;
}
__device__ __forceinline__ void cp16(uint32_t dst, const void* src) {
    asm volatile("cp.async.cg.shared.global [%0], [%1], 16;" :: "r"(dst), "l"(src));
}
#define CP_COMMIT() asm volatile("cp.async.commit_group;" ::: "memory")
#define CP_WAIT1()  asm volatile("cp.async.wait_group 1;" ::: "memory")

__device__ __forceinline__ void ldm_x4(uint32_t* r, uint32_t addr) {
    asm volatile("ldmatrix.sync.aligned.m8n8.x4.shared.b16 {%0,%1,%2,%3}, [%4];"
                 : "=r"(r[0]), "=r"(r[1]), "=r"(r[2]), "=r"(r[3]) : "r"(addr));
}
__device__ __forceinline__ void mma16816(float* c, const uint32_t* a, uint32_t b0, uint32_t b1) {
    asm volatile("mma.sync.aligned.m16n8k16.row.col.f32.bf16.bf16.f32 "
                 "{%0,%1,%2,%3}, {%4,%5,%6,%7}, {%8,%9}, {%0,%1,%2,%3};"
                 : "+f"(c[0]), "+f"(c[1]), "+f"(c[2]), "+f"(c[3])
                 : "r"(a[0]), "r"(a[1]), "r"(a[2]), "r"(a[3]), "r"(b0), "r"(b1));
}
__device__ __forceinline__ void split2(float v, __nv_bfloat16& hi, __nv_bfloat16& lo) {
    hi = __float2bfloat16(v);
    lo = __float2bfloat16(v - __bfloat162float(hi));
}

// BK=64: A tile 128x72 bf16 (144 B/row), B tile 256x72 bf16
#define A_TILE 18432                  // 128*144
#define B_TILE 36864                  // 256*144
#define STAGE_BYTES (A_TILE + B_TILE) // 55296
#define MMA_SMEM (3 * STAGE_BYTES)    // 165888

// mainloop: CTA 128x256 tile, 8 warps as 2(m) x 4(n), warp 64x64, K=niter*64
// fragment double-buffered: ldsm(kk+1) issued before mma(kk) burst
__device__ __forceinline__ void mma_mainloop(
    uint32_t smb, const __nv_bfloat16* __restrict__ Ab,
    const __nv_bfloat16* __restrict__ Bb, int sA, int sB, int niter,
    int t, int lane, int wm, int wn, float c[4][8][4])
{
    uint32_t aoff[4], boff[4];
    {
        int lr = lane & 15, lc = lane >> 4;
        #pragma unroll
        for (int mi = 0; mi < 4; mi++) aoff[mi] = (wm * 64 + mi * 16 + lr) * 144 + lc * 16;
        #pragma unroll
        for (int nj = 0; nj < 4; nj++) boff[nj] = A_TILE + (wn * 64 + nj * 16 + lr) * 144 + lc * 16;
    }
    int lrow = t >> 3;
    int lc16 = (t & 7) * 16;
    int lcol_el = (t & 7) * 8;

    // prologue: stages 0,1
    #pragma unroll
    for (int s = 0; s < 2; s++) {
        uint32_t db = smb + s * STAGE_BYTES;
        #pragma unroll
        for (int i = 0; i < 4; i++) {
            int row = lrow + i * 32;
            cp16(db + row * 144 + lc16, Ab + (size_t)row * sA + s * 64 + lcol_el);
        }
        #pragma unroll
        for (int i = 0; i < 8; i++) {
            int row = lrow + i * 32;
            cp16(db + A_TILE + row * 144 + lc16, Bb + (size_t)row * sB + s * 64 + lcol_el);
        }
        CP_COMMIT();
    }

    for (int ck = 0; ck < niter; ck++) {
        CP_WAIT1();
        __syncthreads();
        int pf = ck + 2;
        if (pf < niter) {
            uint32_t db = smb + (pf % 3) * STAGE_BYTES;
            #pragma unroll
            for (int i = 0; i < 4; i++) {
                int row = lrow + i * 32;
                cp16(db + row * 144 + lc16, Ab + (size_t)row * sA + pf * 64 + lcol_el);
            }
            #pragma unroll
            for (int i = 0; i < 8; i++) {
                int row = lrow + i * 32;
                cp16(db + A_TILE + row * 144 + lc16, Bb + (size_t)row * sB + pf * 64 + lcol_el);
            }
        }
        CP_COMMIT();
        uint32_t sa = smb + (ck % 3) * STAGE_BYTES;

        uint32_t a[2][4][4], b[2][4][4];
        // preload kk=0 fragments
        #pragma unroll
        for (int mi = 0; mi < 4; mi++) ldm_x4(a[0][mi], sa + aoff[mi]);
        #pragma unroll
        for (int nj = 0; nj < 4; nj++) ldm_x4(b[0][nj], sa + boff[nj]);

        #pragma unroll
        for (int kk = 0; kk < 4; kk++) {
            int cur = kk & 1, nxt = cur ^ 1;
            if (kk < 3) {   // issue next-kk loads BEFORE the mma burst (latency hidden)
                #pragma unroll
                for (int mi = 0; mi < 4; mi++) ldm_x4(a[nxt][mi], sa + aoff[mi] + (kk + 1) * 32);
                #pragma unroll
                for (int nj = 0; nj < 4; nj++) ldm_x4(b[nxt][nj], sa + boff[nj] + (kk + 1) * 32);
            }
            #pragma unroll
            for (int mi = 0; mi < 4; mi++)
                #pragma unroll
                for (int ni = 0; ni < 8; ni++)
                    mma16816(c[mi][ni], a[cur][mi],
                             b[cur][ni >> 1][ni & 1], b[cur][ni >> 1][(ni & 1) + 2]);
        }
    }
}

// ---------------- K1: pool + rmsnorm + gelu -> bf16 splits ----------------
__global__ void k_pool(const float* __restrict__ x, const float* __restrict__ w_rms,
                       __nv_bfloat16* __restrict__ Xn, __nv_bfloat16* __restrict__ Xg) {
    int sp = blockIdx.x;
    const float* xb = x + (size_t)sp * 16 * DIN;
    __shared__ float xp[DIN];
    __shared__ float red[256];
    int t = threadIdx.x;
    float ssq = 0.f;
    for (int c = t; c < DIN; c += 256) {
        float s = 0.f;
        #pragma unroll
        for (int r = 0; r < 16; r++) s += xb[r * DIN + c];
        s *= (1.f / 16.f);
        xp[c] = s;
        ssq += s * s;
    }
    red[t] = ssq;
    __syncthreads();
    for (int o = 128; o > 0; o >>= 1) {
        if (t < o) red[t] += red[t + o];
        __syncthreads();
    }
    float scale = rsqrtf(red[0] / (float)DIN + 1e-6f);
    size_t b = (size_t)sp * K3;
    for (int c = t; c < DIN; c += 256) {
        float v = xp[c] * scale * w_rms[c];
        __nv_bfloat16 hi, lo;
        split2(v, hi, lo);
        Xn[b + c] = hi; Xn[b + DIN + c] = hi; Xn[b + 2 * DIN + c] = lo;
        float g = v * normcdff(v);
        split2(g, hi, lo);
        Xg[b + c] = hi; Xg[b + DIN + c] = hi; Xg[b + 2 * DIN + c] = lo;
    }
}

// ---------------- K2: f0 table ----------------
__global__ void k_f0(int* __restrict__ f0) {
    int d = threadIdx.x;
    if (d < SP) {
        const float log_step = (float)(log(481.0) / 32.0);
        int cnt = 0;
        #pragma unroll
        for (int f = 0; f < 32; f++) {
            float cw = (float)f + expf((float)f * log_step);
            if (cw <= (float)d) cnt++;
        }
        f0[d] = cnt;
    }
}

// ---------------- K4: transpose + split weights [hi,lo,hi] ----------------
__global__ void k_wsplit(const float* __restrict__ srcA, const float* __restrict__ srcB,
                         int Nsrc, __nv_bfloat16* __restrict__ dst) {
    __shared__ float tile[32][33];
    int t = threadIdx.x;
    int n0 = blockIdx.x * 32, k0 = blockIdx.y * 32;
    const float* src = (n0 < Nsrc) ? srcA : srcB;
    int nb = (n0 < Nsrc) ? n0 : (n0 - Nsrc);
    #pragma unroll
    for (int i = 0; i < 4; i++) {
        int r = (t >> 5) + i * 8, c = t & 31;
        tile[r][c] = src[(size_t)(k0 + r) * Nsrc + nb + c];
    }
    __syncthreads();
    #pragma unroll
    for (int i = 0; i < 4; i++) {
        int rn = (t >> 5) + i * 8;
        int kk = k0 + (t & 31);
        float v = tile[t & 31][rn];
        __nv_bfloat16 hi, lo;
        split2(v, hi, lo);
        size_t row = (size_t)(n0 + rn) * K3;
        dst[row + kk] = hi;
        dst[row + DIN + kk] = lo;
        dst[row + 2 * DIN + kk] = hi;
    }
}

// ---------------- K5: fused projection GEMM (CTA 128x256) ----------------
__global__ void __launch_bounds__(256) k_proj(
    const __nv_bfloat16* __restrict__ Xn, const __nv_bfloat16* __restrict__ Xg,
    const __nv_bfloat16* __restrict__ Ww, const __nv_bfloat16* __restrict__ Wy,
    float* __restrict__ q, float* __restrict__ k,
    float* __restrict__ yq, float* __restrict__ yk)
{
    extern __shared__ char sm[];
    uint32_t smb = smem_u32(sm);
    int t = threadIdx.x, w = t >> 5, lane = t & 31;
    int wm = w >> 2, wn = w & 3;
    int bid = blockIdx.x;
    int mt, nt;
    if (bid < 128) { mt = bid & 3; nt = bid >> 2; }
    else { mt = bid - 128; nt = 32; }

    const __nv_bfloat16* Ab = (bid < 128) ? (Xn + (size_t)mt * 128 * K3)
                                          : (Xg + (size_t)mt * 128 * K3);
    const __nv_bfloat16* Bb = (nt < 32) ? (Ww + (size_t)nt * 256 * K3) : Wy;

    float c[4][8][4];
    #pragma unroll
    for (int i = 0; i < 4; i++)
        #pragma unroll
        for (int j = 0; j < 8; j++)
            #pragma unroll
            for (int e = 0; e < 4; e++) c[i][j][e] = 0.f;

    mma_mainloop(smb, Ab, Bb, K3, K3, K3 / 64, t, lane, wm, wn, c);

    int r0 = lane >> 2, c0 = (lane & 3) * 2;
    int srow0 = mt * 128;
    #pragma unroll
    for (int mi = 0; mi < 4; mi++) {
        #pragma unroll
        for (int ni = 0; ni < 8; ni++) {
            #pragma unroll
            for (int half = 0; half < 2; half++) {
                int s = srow0 + wm * 64 + mi * 16 + r0 + half * 8;
                int colL = wn * 64 + ni * 8 + c0;
                float2 fv = make_float2(c[mi][ni][half * 2], c[mi][ni][half * 2 + 1]);
                if (nt < 32) {
                    int col = nt * 256 + colL;
                    bool isQ = col < HDTOT;
                    float* o = isQ ? q : k;
                    int nn = isQ ? col : col - HDTOT;
                    *(float2*)&o[(size_t)s * HDTOT + nn] = fv;
                } else {
                    float* o = (colL < HD) ? yq : yk;
                    int nn = (colL < HD) ? colL : colL - HD;
                    *(float2*)&o[(size_t)s * HD + nn] = fv;
                }
            }
        }
    }
}

// ---------------- K5s: scores GEMM (CTA 128x256, batched over heads) ----------------
__global__ void __launch_bounds__(256) k_scores(
    const __nv_bfloat16* __restrict__ Qs, const __nv_bfloat16* __restrict__ Ks,
    float* __restrict__ S)
{
    extern __shared__ char sm[];
    uint32_t smb = smem_u32(sm);
    int t = threadIdx.x, w = t >> 5, lane = t & 31;
    int wm = w >> 2, wn = w & 3;
    int m0 = blockIdx.x * 128, n0 = blockIdx.y * 256, z = blockIdx.z;

    const __nv_bfloat16* Ab = Qs + (size_t)z * SP * KH + (size_t)m0 * KH;
    const __nv_bfloat16* Bb = Ks + (size_t)z * SP * KH + (size_t)n0 * KH;

    float c[4][8][4];
    #pragma unroll
    for (int i = 0; i < 4; i++)
        #pragma unroll
        for (int j = 0; j < 8; j++)
            #pragma unroll
            for (int e = 0; e < 4; e++) c[i][j][e] = 0.f;

    mma_mainloop(smb, Ab, Bb, KH, KH, KH / 64, t, lane, wm, wn, c);

    int r0 = lane >> 2, c0 = (lane & 3) * 2;
    #pragma unroll
    for (int mi = 0; mi < 4; mi++) {
        #pragma unroll
        for (int ni = 0; ni < 8; ni++) {
            #pragma unroll
            for (int half = 0; half < 2; half++) {
                int row = m0 + wm * 64 + mi * 16 + r0 + half * 8;
                int col = n0 + wn * 64 + ni * 8 + c0;
                float2 fv = make_float2(c[mi][ni][half * 2], c[mi][ni][half * 2 + 1]);
                *(float2*)&S[((size_t)(z * SP + row)) * SP + col] = fv;
            }
        }
    }
}

// ---------------- K5b: coalesced split of q/k -> Qs/Ks ----------------
__global__ void k_splitqk(const float* __restrict__ q, const float* __restrict__ k,
                          __nv_bfloat16* __restrict__ Qs, __nv_bfloat16* __restrict__ Ks) {
    int idx = blockIdx.x * 256 + threadIdx.x;
    int s = idx >> 12, n = idx & 4095;
    int h = n >> 7, c = n & 127;
    size_t base = ((size_t)h * SP + s) * KH + c;
    __nv_bfloat16 hi, lo;
    split2(q[idx], hi, lo);
    Qs[base] = hi; Qs[base + 128] = lo; Qs[base + 256] = hi;
    split2(k[idx], hi, lo);
    Ks[base] = hi; Ks[base + 128] = hi; Ks[base + 256] = lo;
}

// ---------------- K6: suffix tables ----------------
__global__ void __launch_bounds__(256) k_suffix(const float* __restrict__ qk,
                                                const float* __restrict__ rbias,
                                                const float* __restrict__ W_pos,
                                                const float* __restrict__ b_pos,
                                                float* __restrict__ T) {
    extern __shared__ float smf[];
    float* ws = smf;
    float* qs = ws + 65 * 132;
    float* Ms = qs + 32 * 132;
    int h = blockIdx.y;
    int q0 = blockIdx.x * 32;
    int t = threadIdx.x;
    for (int i = t; i < 65 * 128; i += 256) {
        int f = i >> 7, c = i & 127;
        ws[f * 132 + c] = (f < 64) ? W_pos[f * HDTOT + h * HD + c] : b_pos[h * HD + c];
    }
    for (int i = t; i < 32 * 128; i += 256) {
        int r = i >> 7, c = i & 127;
        qs[r * 132 + c] = qk[(size_t)(q0 + r) * HDTOT + h * HD + c] + rbias[h * HD + c];
    }
    __syncthreads();
    for (int i = t; i < 32 * 65; i += 256) {
        int r = i / 65, f = i % 65;
        const float4* qr = (const float4*)&qs[r * 132];
        const float4* wr = (const float4*)&ws[f * 132];
        float acc = 0.f;
        #pragma unroll
        for (int c4 = 0; c4 < 32; c4++) {
            float4 a = qr[c4], b = wr[c4];
            acc += a.x * b.x + a.y * b.y + a.z * b.z + a.w * b.w;
        }
        Ms[r * 65 + f] = acc;
    }
    __syncthreads();
    for (int i = t; i < 32 * 33; i += 256) {
        int r = i / 33, j = i % 33;
        float sa = Ms[r * 65 + 64];
        float sb = 0.f;
        for (int f = j; f < 32; f++) { sa += Ms[r * 65 + f]; sb += Ms[r * 65 + 32 + f]; }
        int q = q0 + r;
        T[((j * SP + q) * NH + h) * 2] = sa;
        T[((j * SP + q) * NH + h) * 2 + 1] = sb;
    }
}

// ---------------- K7: fold suffix tables through W_pair ----------------
__global__ void __launch_bounds__(128) k_fold(const float* __restrict__ TQ,
                                              const float* __restrict__ TK,
                                              const float* __restrict__ Wp,
                                              float* __restrict__ RQ,
                                              float* __restrict__ RK) {
    __shared__ float tq[33 * 64], tk[33 * 64];
    int q = blockIdx.x, t = threadIdx.x;
    for (int i = t; i < 33 * 64; i += 128) {
        int j = i >> 6, r = i & 63;
        tq[i] = TQ[((size_t)j * SP + q) * 64 + r];
        tk[i] = TK[((size_t)j * SP + q) * 64 + r];
    }
    float wcol[NH];
    #pragma unroll
    for (int h = 0; h < NH; h++) wcol[h] = Wp[h * HD + t];
    __syncthreads();
    for (int j = 0; j < 33; j++) {
        float aa = 0.f, ab = 0.f, ba = 0.f, bb = 0.f;
        const float* tqj = &tq[j * 64];
        const float* tkj = &tk[j * 64];
        #pragma unroll
        for (int h = 0; h < NH; h++) {
            float w = wcol[h];
            aa += tqj[2 * h] * w;  ab += tqj[2 * h + 1] * w;
            ba += tkj[2 * h] * w;  bb += tkj[2 * h + 1] * w;
        }
        size_t ob = ((size_t)j * SP + q) * 256 + t * 2;
        RQ[ob] = aa; RQ[ob + 1] = ab;
        RK[ob] = ba; RK[ob + 1] = bb;
    }
}

// ---------------- K8: final pass (FFMA) ----------------
__global__ void __launch_bounds__(256) k_pair2(const float* __restrict__ S,
                                               const float* __restrict__ RQ,
                                               const float* __restrict__ RK,
                                               const int* __restrict__ f0tab,
                                               const float* __restrict__ Wp,
                                               const float* __restrict__ bp,
                                               const float* __restrict__ yq,
                                               const float* __restrict__ yk,
                                               float* __restrict__ out) {
    __shared__ float Sh[128 * 36];
    int t = threadIdx.x;
    int q = blockIdx.x, k0 = blockIdx.y * 128;
    for (int i = t; i < 4096; i += 256) {
        int h = i >> 7, kk = i & 127;
        Sh[kk * 36 + h] = S[(((size_t)h * SP + q) << 9) + k0 + kk];
    }
    int d = t & 127, g = t >> 7;
    float wcol[NH];
    #pragma unroll
    for (int h = 0; h < NH; h++) wcol[h] = Wp[h * HD + d];
    float base0 = bp[d] + yq[q * HD + d];
    __syncthreads();
    for (int kk = g * 64; kk < g * 64 + 64; kk++) {
        int k = k0 + kk;
        int delta = k - q;
        int dd = delta >= 0 ? delta : -delta;
        float sgn = delta > 0 ? 1.f : (delta < 0 ? -1.f : 0.f);
        int j = f0tab[dd];
        float2 rq = *(const float2*)&RQ[((size_t)j * SP + q) * 256 + d * 2];
        float2 rk = *(const float2*)&RK[((size_t)j * SP + k) * 256 + d * 2];
        float acc = base0 + yk[k * HD + d]
                  + 0.5f * (rq.x + rk.x) + 0.5f * sgn * (rq.y - rk.y);
        const float* sr = &Sh[kk * 36];
        #pragma unroll
        for (int h4 = 0; h4 < 8; h4++) {
            float4 sv = *(const float4*)&sr[h4 * 4];
            acc += sv.x * wcol[h4 * 4] + sv.y * wcol[h4 * 4 + 1] +
                   sv.z * wcol[h4 * 4 + 2] + sv.w * wcol[h4 * 4 + 3];
        }
        out[((size_t)(q * SP + k)) * HD + d] = acc;
    }
}

// ---------------- launcher ----------------
#define SUF_SMEM ((65 * 132 + 32 * 132 + 32 * 65) * 4)

extern "C" void kernel_launch(void* const* d_in, const int* in_sizes, int n_in,
                              void* d_out, int out_size) {
    const float* x      = (const float*)d_in[0];
    const float* w_rms  = (const float*)d_in[1];
    const float* W_q    = (const float*)d_in[2];
    const float* W_k    = (const float*)d_in[3];
    const float* W_pos  = (const float*)d_in[4];
    const float* b_pos  = (const float*)d_in[5];
    const float* qrb    = (const float*)d_in[6];
    const float* krb    = (const float*)d_in[7];
    const float* W_yq   = (const float*)d_in[8];
    const float* W_yk   = (const float*)d_in[9];
    const float* W_pair = (const float*)d_in[10];
    const float* b_pair = (const float*)d_in[11];
    float* out = (float*)d_out;

    float *qb, *kb, *yq, *yk, *TQ, *TK, *RQ, *RK, *Sb;
    __nv_bfloat16 *Xn, *Xg, *Ww, *Wy, *Qs, *Ks;
    int* f0;
    cudaGetSymbolAddress((void**)&qb, g_q);
    cudaGetSymbolAddress((void**)&kb, g_k);
    cudaGetSymbolAddress((void**)&yq, g_yq);
    cudaGetSymbolAddress((void**)&yk, g_yk);
    cudaGetSymbolAddress((void**)&TQ, g_TQ);
    cudaGetSymbolAddress((void**)&TK, g_TK);
    cudaGetSymbolAddress((void**)&RQ, g_RQ);
    cudaGetSymbolAddress((void**)&RK, g_RK);
    cudaGetSymbolAddress((void**)&Sb, g_S);
    cudaGetSymbolAddress((void**)&Xn, g_Xn);
    cudaGetSymbolAddress((void**)&Xg, g_Xg);
    cudaGetSymbolAddress((void**)&Ww, g_Ww);
    cudaGetSymbolAddress((void**)&Wy, g_Wy);
    cudaGetSymbolAddress((void**)&Qs, g_Qs);
    cudaGetSymbolAddress((void**)&Ks, g_Ks);
    cudaGetSymbolAddress((void**)&f0, g_f0);

    cudaFuncSetAttribute(k_proj, cudaFuncAttributeMaxDynamicSharedMemorySize, MMA_SMEM);
    cudaFuncSetAttribute(k_scores, cudaFuncAttributeMaxDynamicSharedMemorySize, MMA_SMEM);
    cudaFuncSetAttribute(k_suffix, cudaFuncAttributeMaxDynamicSharedMemorySize, SUF_SMEM);

    k_pool<<<SP, 256>>>(x, w_rms, Xn, Xg);                                  // idx 0
    k_wsplit<<<dim3(2 * HD / 32, DIN / 32), 256>>>(W_yq, W_yk, HD, Wy);     // idx 1
    k_wsplit<<<dim3(2 * HDTOT / 32, DIN / 32), 256>>>(W_q, W_k, HDTOT, Ww); // idx 2
    k_proj<<<132, 256, MMA_SMEM>>>(Xn, Xg, Ww, Wy, qb, kb, yq, yk);         // idx 3 (profiled)
    k_f0<<<1, 512>>>(f0);                                                   // idx 4

    k_splitqk<<<SP * HDTOT / 256, 256>>>(qb, kb, Qs, Ks);

    dim3 gs(SP / 32, NH);
    k_suffix<<<gs, 256, SUF_SMEM>>>(qb, qrb, W_pos, b_pos, TQ);
    k_suffix<<<gs, 256, SUF_SMEM>>>(kb, krb, W_pos, b_pos, TK);
    k_fold<<<SP, 128>>>(TQ, TK, W_pair, RQ, RK);

    k_scores<<<dim3(4, 2, NH), 256, MMA_SMEM>>>(Qs, Ks, Sb);

    k_pair2<<<dim3(SP, 4), 256>>>(Sb, RQ, RK, f0, W_pair, b_pair, yq, yk, out);
}

// round 10
// speedup vs baseline: 2.8189x; 1.1268x over previous
#include <cuda_runtime.h>
#include <cuda_fp16.h>
#include <math.h>
#include <stdint.h>

#define SP    512
#define DIN   1536
#define NH    32
#define HD    128
#define HDTOT 4096
#define KS    3072   // 2*DIN  (fp16 2-term split)
#define KHS   256    // 2*HD

// ---------------- scratch ----------------
__device__ __half g_Xn[SP*KS];                    // x_norm  [hi,lo]
__device__ __half g_Xg[SP*KS];                    // x_gelu  [hi,lo]
__device__ __half g_Ww[(size_t)2*HDTOT*KS];       // Wq|Wk transposed [hi,hi]
__device__ __half g_Wy[2*HD*KS];                  // Wyq|Wyk transposed [hi,hi]
__device__ float g_q[SP*HDTOT];
__device__ float g_k[SP*HDTOT];
__device__ float g_yq[SP*HD];
__device__ float g_yk[SP*HD];
__device__ __half g_Qs[(size_t)NH*SP*KHS];        // [h][s][256] [hi,lo]
__device__ __half g_Ks[(size_t)NH*SP*KHS];        // [h][s][256] [hi,hi]
__device__ float g_S[(size_t)NH*SP*SP];
__device__ float g_TQ[33*SP*NH*2];
__device__ float g_TK[33*SP*NH*2];
__device__ float g_RQ[33*SP*HD*2];
__device__ float g_RK[33*SP*HD*2];
__device__ int   g_f0[SP];

// ---------------- helpers ----------------
__device__ __forceinline__ uint32_t smem_u32(const void* p) {
    uint32_t a;
    asm("{ .reg .u64 t; cvta.to.shared.u64 t, %1; cvt.u32.u64 %0, t; }" : "=r"(a) : "l"(p));
    return a;
}
__device__ __forceinline__ void cp16(uint32_t dst, const void* src) {
    asm volatile("cp.async.cg.shared.global [%0], [%1], 16;" :: "r"(dst), "l"(src));
}
#define CP_COMMIT() asm volatile("cp.async.commit_group;" ::: "memory")
#define CP_WAIT1()  asm volatile("cp.async.wait_group 1;" ::: "memory")

__device__ __forceinline__ void ldm_x4(uint32_t* r, uint32_t addr) {
    asm volatile("ldmatrix.sync.aligned.m8n8.x4.shared.b16 {%0,%1,%2,%3}, [%4];"
                 : "=r"(r[0]), "=r"(r[1]), "=r"(r[2]), "=r"(r[3]) : "r"(addr));
}
__device__ __forceinline__ void mma16816(float* c, const uint32_t* a, uint32_t b0, uint32_t b1) {
    asm volatile("mma.sync.aligned.m16n8k16.row.col.f32.f16.f16.f32 "
                 "{%0,%1,%2,%3}, {%4,%5,%6,%7}, {%8,%9}, {%0,%1,%2,%3};"
                 : "+f"(c[0]), "+f"(c[1]), "+f"(c[2]), "+f"(c[3])
                 : "r"(a[0]), "r"(a[1]), "r"(a[2]), "r"(a[3]), "r"(b0), "r"(b1));
}
__device__ __forceinline__ void split2h(float v, __half& hi, __half& lo) {
    hi = __float2half(v);
    lo = __float2half(v - __half2float(hi));
}

// BK=64: A tile 128x72 fp16 (144 B/row), B tile 256x72 fp16
#define A_TILE 18432                  // 128*144
#define B_TILE 36864                  // 256*144
#define STAGE_BYTES (A_TILE + B_TILE) // 55296
#define MMA_SMEM (3 * STAGE_BYTES)    // 165888

// mainloop: CTA 128x256 tile, 8 warps as 2(m) x 4(n), warp 64x64, K=niter*64
__device__ __forceinline__ void mma_mainloop(
    uint32_t smb, const __half* __restrict__ Ab,
    const __half* __restrict__ Bb, int sA, int sB, int niter,
    int t, int lane, int wm, int wn, float c[4][8][4])
{
    uint32_t aoff[4], boff[4];
    {
        int lr = lane & 15, lc = lane >> 4;
        #pragma unroll
        for (int mi = 0; mi < 4; mi++) aoff[mi] = (wm * 64 + mi * 16 + lr) * 144 + lc * 16;
        #pragma unroll
        for (int nj = 0; nj < 4; nj++) boff[nj] = A_TILE + (wn * 64 + nj * 16 + lr) * 144 + lc * 16;
    }
    int lrow = t >> 3;
    int lc16 = (t & 7) * 16;
    int lcol_el = (t & 7) * 8;

    #pragma unroll
    for (int s = 0; s < 2; s++) {
        uint32_t db = smb + s * STAGE_BYTES;
        #pragma unroll
        for (int i = 0; i < 4; i++) {
            int row = lrow + i * 32;
            cp16(db + row * 144 + lc16, Ab + (size_t)row * sA + s * 64 + lcol_el);
        }
        #pragma unroll
        for (int i = 0; i < 8; i++) {
            int row = lrow + i * 32;
            cp16(db + A_TILE + row * 144 + lc16, Bb + (size_t)row * sB + s * 64 + lcol_el);
        }
        CP_COMMIT();
    }

    for (int ck = 0; ck < niter; ck++) {
        CP_WAIT1();
        __syncthreads();
        int pf = ck + 2;
        if (pf < niter) {
            uint32_t db = smb + (pf % 3) * STAGE_BYTES;
            #pragma unroll
            for (int i = 0; i < 4; i++) {
                int row = lrow + i * 32;
                cp16(db + row * 144 + lc16, Ab + (size_t)row * sA + pf * 64 + lcol_el);
            }
            #pragma unroll
            for (int i = 0; i < 8; i++) {
                int row = lrow + i * 32;
                cp16(db + A_TILE + row * 144 + lc16, Bb + (size_t)row * sB + pf * 64 + lcol_el);
            }
        }
        CP_COMMIT();
        uint32_t sa = smb + (ck % 3) * STAGE_BYTES;
        #pragma unroll
        for (int kk = 0; kk < 4; kk++) {
            uint32_t a[4][4], b[4][4];
            #pragma unroll
            for (int mi = 0; mi < 4; mi++) ldm_x4(a[mi], sa + aoff[mi] + kk * 32);
            #pragma unroll
            for (int nj = 0; nj < 4; nj++) ldm_x4(b[nj], sa + boff[nj] + kk * 32);
            #pragma unroll
            for (int mi = 0; mi < 4; mi++)
                #pragma unroll
                for (int ni = 0; ni < 8; ni++)
                    mma16816(c[mi][ni], a[mi], b[ni >> 1][ni & 1], b[ni >> 1][(ni & 1) + 2]);
        }
    }
}

// ---------------- K1: pool + rmsnorm + gelu -> fp16 [hi,lo] ----------------
__global__ void k_pool(const float* __restrict__ x, const float* __restrict__ w_rms,
                       __half* __restrict__ Xn, __half* __restrict__ Xg) {
    int sp = blockIdx.x;
    const float* xb = x + (size_t)sp * 16 * DIN;
    __shared__ float xp[DIN];
    __shared__ float red[256];
    int t = threadIdx.x;
    float ssq = 0.f;
    for (int c = t; c < DIN; c += 256) {
        float s = 0.f;
        #pragma unroll
        for (int r = 0; r < 16; r++) s += xb[r * DIN + c];
        s *= (1.f / 16.f);
        xp[c] = s;
        ssq += s * s;
    }
    red[t] = ssq;
    __syncthreads();
    for (int o = 128; o > 0; o >>= 1) {
        if (t < o) red[t] += red[t + o];
        __syncthreads();
    }
    float scale = rsqrtf(red[0] / (float)DIN + 1e-6f);
    size_t b = (size_t)sp * KS;
    for (int c = t; c < DIN; c += 256) {
        float v = xp[c] * scale * w_rms[c];
        __half hi, lo;
        split2h(v, hi, lo);
        Xn[b + c] = hi; Xn[b + DIN + c] = lo;
        float g = v * normcdff(v);
        split2h(g, hi, lo);
        Xg[b + c] = hi; Xg[b + DIN + c] = lo;
    }
}

// ---------------- K2: f0 table ----------------
__global__ void k_f0(int* __restrict__ f0) {
    int d = threadIdx.x;
    if (d < SP) {
        const float log_step = (float)(log(481.0) / 32.0);
        int cnt = 0;
        #pragma unroll
        for (int f = 0; f < 32; f++) {
            float cw = (float)f + expf((float)f * log_step);
            if (cw <= (float)d) cnt++;
        }
        f0[d] = cnt;
    }
}

// ---------------- K4: transpose weights -> fp16 [hi,hi] ----------------
__global__ void k_wsplit(const float* __restrict__ srcA, const float* __restrict__ srcB,
                         int Nsrc, __half* __restrict__ dst) {
    __shared__ float tile[32][33];
    int t = threadIdx.x;
    int n0 = blockIdx.x * 32, k0 = blockIdx.y * 32;
    const float* src = (n0 < Nsrc) ? srcA : srcB;
    int nb = (n0 < Nsrc) ? n0 : (n0 - Nsrc);
    #pragma unroll
    for (int i = 0; i < 4; i++) {
        int r = (t >> 5) + i * 8, c = t & 31;
        tile[r][c] = src[(size_t)(k0 + r) * Nsrc + nb + c];
    }
    __syncthreads();
    #pragma unroll
    for (int i = 0; i < 4; i++) {
        int rn = (t >> 5) + i * 8;
        int kk = k0 + (t & 31);
        __half hi = __float2half(tile[t & 31][rn]);
        size_t row = (size_t)(n0 + rn) * KS;
        dst[row + kk] = hi;
        dst[row + DIN + kk] = hi;
    }
}

// ---------------- K5: fused projection GEMM (CTA 128x256) ----------------
__global__ void __launch_bounds__(256) k_proj(
    const __half* __restrict__ Xn, const __half* __restrict__ Xg,
    const __half* __restrict__ Ww, const __half* __restrict__ Wy,
    float* __restrict__ q, float* __restrict__ k,
    float* __restrict__ yq, float* __restrict__ yk)
{
    extern __shared__ char sm[];
    uint32_t smb = smem_u32(sm);
    int t = threadIdx.x, w = t >> 5, lane = t & 31;
    int wm = w >> 2, wn = w & 3;
    int bid = blockIdx.x;
    int mt, nt;
    if (bid < 128) { mt = bid & 3; nt = bid >> 2; }
    else { mt = bid - 128; nt = 32; }

    const __half* Ab = (bid < 128) ? (Xn + (size_t)mt * 128 * KS)
                                   : (Xg + (size_t)mt * 128 * KS);
    const __half* Bb = (nt < 32) ? (Ww + (size_t)nt * 256 * KS) : Wy;

    float c[4][8][4];
    #pragma unroll
    for (int i = 0; i < 4; i++)
        #pragma unroll
        for (int j = 0; j < 8; j++)
            #pragma unroll
            for (int e = 0; e < 4; e++) c[i][j][e] = 0.f;

    mma_mainloop(smb, Ab, Bb, KS, KS, KS / 64, t, lane, wm, wn, c);

    int r0 = lane >> 2, c0 = (lane & 3) * 2;
    int srow0 = mt * 128;
    #pragma unroll
    for (int mi = 0; mi < 4; mi++) {
        #pragma unroll
        for (int ni = 0; ni < 8; ni++) {
            #pragma unroll
            for (int half = 0; half < 2; half++) {
                int s = srow0 + wm * 64 + mi * 16 + r0 + half * 8;
                int colL = wn * 64 + ni * 8 + c0;
                float2 fv = make_float2(c[mi][ni][half * 2], c[mi][ni][half * 2 + 1]);
                if (nt < 32) {
                    int col = nt * 256 + colL;
                    bool isQ = col < HDTOT;
                    float* o = isQ ? q : k;
                    int nn = isQ ? col : col - HDTOT;
                    *(float2*)&o[(size_t)s * HDTOT + nn] = fv;
                } else {
                    float* o = (colL < HD) ? yq : yk;
                    int nn = (colL < HD) ? colL : colL - HD;
                    *(float2*)&o[(size_t)s * HD + nn] = fv;
                }
            }
        }
    }
}

// ---------------- K5s: scores GEMM (CTA 128x256, batched over heads) ----------------
__global__ void __launch_bounds__(256) k_scores(
    const __half* __restrict__ Qs, const __half* __restrict__ Ks,
    float* __restrict__ S)
{
    extern __shared__ char sm[];
    uint32_t smb = smem_u32(sm);
    int t = threadIdx.x, w = t >> 5, lane = t & 31;
    int wm = w >> 2, wn = w & 3;
    int m0 = blockIdx.x * 128, n0 = blockIdx.y * 256, z = blockIdx.z;

    const __half* Ab = Qs + (size_t)z * SP * KHS + (size_t)m0 * KHS;
    const __half* Bb = Ks + (size_t)z * SP * KHS + (size_t)n0 * KHS;

    float c[4][8][4];
    #pragma unroll
    for (int i = 0; i < 4; i++)
        #pragma unroll
        for (int j = 0; j < 8; j++)
            #pragma unroll
            for (int e = 0; e < 4; e++) c[i][j][e] = 0.f;

    mma_mainloop(smb, Ab, Bb, KHS, KHS, KHS / 64, t, lane, wm, wn, c);

    int r0 = lane >> 2, c0 = (lane & 3) * 2;
    #pragma unroll
    for (int mi = 0; mi < 4; mi++) {
        #pragma unroll
        for (int ni = 0; ni < 8; ni++) {
            #pragma unroll
            for (int half = 0; half < 2; half++) {
                int row = m0 + wm * 64 + mi * 16 + r0 + half * 8;
                int col = n0 + wn * 64 + ni * 8 + c0;
                float2 fv = make_float2(c[mi][ni][half * 2], c[mi][ni][half * 2 + 1]);
                *(float2*)&S[((size_t)(z * SP + row)) * SP + col] = fv;
            }
        }
    }
}

// ---------------- K5b: coalesced split of q/k -> Qs/Ks ----------------
__global__ void k_splitqk(const float* __restrict__ q, const float* __restrict__ k,
                          __half* __restrict__ Qs, __half* __restrict__ Ks) {
    int idx = blockIdx.x * 256 + threadIdx.x;
    int s = idx >> 12, n = idx & 4095;
    int h = n >> 7, c = n & 127;
    size_t base = ((size_t)h * SP + s) * KHS + c;
    __half hi, lo;
    split2h(q[idx], hi, lo);
    Qs[base] = hi; Qs[base + HD] = lo;
    __half khi = __float2half(k[idx]);
    Ks[base] = khi; Ks[base + HD] = khi;
}

// ---------------- K6: suffix tables ----------------
__global__ void __launch_bounds__(256) k_suffix(const float* __restrict__ qk,
                                                const float* __restrict__ rbias,
                                                const float* __restrict__ W_pos,
                                                const float* __restrict__ b_pos,
                                                float* __restrict__ T) {
    extern __shared__ float smf[];
    float* ws = smf;
    float* qs = ws + 65 * 132;
    float* Ms = qs + 32 * 132;
    int h = blockIdx.y;
    int q0 = blockIdx.x * 32;
    int t = threadIdx.x;
    for (int i = t; i < 65 * 128; i += 256) {
        int f = i >> 7, c = i & 127;
        ws[f * 132 + c] = (f < 64) ? W_pos[f * HDTOT + h * HD + c] : b_pos[h * HD + c];
    }
    for (int i = t; i < 32 * 128; i += 256) {
        int r = i >> 7, c = i & 127;
        qs[r * 132 + c] = qk[(size_t)(q0 + r) * HDTOT + h * HD + c] + rbias[h * HD + c];
    }
    __syncthreads();
    for (int i = t; i < 32 * 65; i += 256) {
        int r = i / 65, f = i % 65;
        const float4* qr = (const float4*)&qs[r * 132];
        const float4* wr = (const float4*)&ws[f * 132];
        float acc = 0.f;
        #pragma unroll
        for (int c4 = 0; c4 < 32; c4++) {
            float4 a = qr[c4], b = wr[c4];
            acc += a.x * b.x + a.y * b.y + a.z * b.z + a.w * b.w;
        }
        Ms[r * 65 + f] = acc;
    }
    __syncthreads();
    for (int i = t; i < 32 * 33; i += 256) {
        int r = i / 33, j = i % 33;
        float sa = Ms[r * 65 + 64];
        float sb = 0.f;
        for (int f = j; f < 32; f++) { sa += Ms[r * 65 + f]; sb += Ms[r * 65 + 32 + f]; }
        int q = q0 + r;
        T[((j * SP + q) * NH + h) * 2] = sa;
        T[((j * SP + q) * NH + h) * 2 + 1] = sb;
    }
}

// ---------------- K7: fold suffix tables through W_pair ----------------
__global__ void __launch_bounds__(128) k_fold(const float* __restrict__ TQ,
                                              const float* __restrict__ TK,
                                              const float* __restrict__ Wp,
                                              float* __restrict__ RQ,
                                              float* __restrict__ RK) {
    __shared__ float tq[33 * 64], tk[33 * 64];
    int q = blockIdx.x, t = threadIdx.x;
    for (int i = t; i < 33 * 64; i += 128) {
        int j = i >> 6, r = i & 63;
        tq[i] = TQ[((size_t)j * SP + q) * 64 + r];
        tk[i] = TK[((size_t)j * SP + q) * 64 + r];
    }
    float wcol[NH];
    #pragma unroll
    for (int h = 0; h < NH; h++) wcol[h] = Wp[h * HD + t];
    __syncthreads();
    for (int j = 0; j < 33; j++) {
        float aa = 0.f, ab = 0.f, ba = 0.f, bb = 0.f;
        const float* tqj = &tq[j * 64];
        const float* tkj = &tk[j * 64];
        #pragma unroll
        for (int h = 0; h < NH; h++) {
            float w = wcol[h];
            aa += tqj[2 * h] * w;  ab += tqj[2 * h + 1] * w;
            ba += tkj[2 * h] * w;  bb += tkj[2 * h + 1] * w;
        }
        size_t ob = ((size_t)j * SP + q) * 256 + t * 2;
        RQ[ob] = aa; RQ[ob + 1] = ab;
        RK[ob] = ba; RK[ob + 1] = bb;
    }
}

// ---------------- K8: final pass (FFMA) ----------------
__global__ void __launch_bounds__(256) k_pair2(const float* __restrict__ S,
                                               const float* __restrict__ RQ,
                                               const float* __restrict__ RK,
                                               const int* __restrict__ f0tab,
                                               const float* __restrict__ Wp,
                                               const float* __restrict__ bp,
                                               const float* __restrict__ yq,
                                               const float* __restrict__ yk,
                                               float* __restrict__ out) {
    __shared__ float Sh[128 * 36];
    int t = threadIdx.x;
    int q = blockIdx.x, k0 = blockIdx.y * 128;
    for (int i = t; i < 4096; i += 256) {
        int h = i >> 7, kk = i & 127;
        Sh[kk * 36 + h] = S[(((size_t)h * SP + q) << 9) + k0 + kk];
    }
    int d = t & 127, g = t >> 7;
    float wcol[NH];
    #pragma unroll
    for (int h = 0; h < NH; h++) wcol[h] = Wp[h * HD + d];
    float base0 = bp[d] + yq[q * HD + d];
    __syncthreads();
    for (int kk = g * 64; kk < g * 64 + 64; kk++) {
        int k = k0 + kk;
        int delta = k - q;
        int dd = delta >= 0 ? delta : -delta;
        float sgn = delta > 0 ? 1.f : (delta < 0 ? -1.f : 0.f);
        int j = f0tab[dd];
        float2 rq = *(const float2*)&RQ[((size_t)j * SP + q) * 256 + d * 2];
        float2 rk = *(const float2*)&RK[((size_t)j * SP + k) * 256 + d * 2];
        float acc = base0 + yk[k * HD + d]
                  + 0.5f * (rq.x + rk.x) + 0.5f * sgn * (rq.y - rk.y);
        const float* sr = &Sh[kk * 36];
        #pragma unroll
        for (int h4 = 0; h4 < 8; h4++) {
            float4 sv = *(const float4*)&sr[h4 * 4];
            acc += sv.x * wcol[h4 * 4] + sv.y * wcol[h4 * 4 + 1] +
                   sv.z * wcol[h4 * 4 + 2] + sv.w * wcol[h4 * 4 + 3];
        }
        out[((size_t)(q * SP + k)) * HD + d] = acc;
    }
}

// ---------------- launcher ----------------
#define SUF_SMEM ((65 * 132 + 32 * 132 + 32 * 65) * 4)

extern "C" void kernel_launch(void* const* d_in, const int* in_sizes, int n_in,
                              void* d_out, int out_size) {
    const float* x      = (const float*)d_in[0];
    const float* w_rms  = (const float*)d_in[1];
    const float* W_q    = (const float*)d_in[2];
    const float* W_k    = (const float*)d_in[3];
    const float* W_pos  = (const float*)d_in[4];
    const float* b_pos  = (const float*)d_in[5];
    const float* qrb    = (const float*)d_in[6];
    const float* krb    = (const float*)d_in[7];
    const float* W_yq   = (const float*)d_in[8];
    const float* W_yk   = (const float*)d_in[9];
    const float* W_pair = (const float*)d_in[10];
    const float* b_pair = (const float*)d_in[11];
    float* out = (float*)d_out;

    float *qb, *kb, *yq, *yk, *TQ, *TK, *RQ, *RK, *Sb;
    __half *Xn, *Xg, *Ww, *Wy, *Qs, *Ks;
    int* f0;
    cudaGetSymbolAddress((void**)&qb, g_q);
    cudaGetSymbolAddress((void**)&kb, g_k);
    cudaGetSymbolAddress((void**)&yq, g_yq);
    cudaGetSymbolAddress((void**)&yk, g_yk);
    cudaGetSymbolAddress((void**)&TQ, g_TQ);
    cudaGetSymbolAddress((void**)&TK, g_TK);
    cudaGetSymbolAddress((void**)&RQ, g_RQ);
    cudaGetSymbolAddress((void**)&RK, g_RK);
    cudaGetSymbolAddress((void**)&Sb, g_S);
    cudaGetSymbolAddress((void**)&Xn, g_Xn);
    cudaGetSymbolAddress((void**)&Xg, g_Xg);
    cudaGetSymbolAddress((void**)&Ww, g_Ww);
    cudaGetSymbolAddress((void**)&Wy, g_Wy);
    cudaGetSymbolAddress((void**)&Qs, g_Qs);
    cudaGetSymbolAddress((void**)&Ks, g_Ks);
    cudaGetSymbolAddress((void**)&f0, g_f0);

    cudaFuncSetAttribute(k_proj, cudaFuncAttributeMaxDynamicSharedMemorySize, MMA_SMEM);
    cudaFuncSetAttribute(k_scores, cudaFuncAttributeMaxDynamicSharedMemorySize, MMA_SMEM);
    cudaFuncSetAttribute(k_suffix, cudaFuncAttributeMaxDynamicSharedMemorySize, SUF_SMEM);

    k_pool<<<SP, 256>>>(x, w_rms, Xn, Xg);                                  // idx 0
    k_wsplit<<<dim3(2 * HD / 32, DIN / 32), 256>>>(W_yq, W_yk, HD, Wy);     // idx 1
    k_wsplit<<<dim3(2 * HDTOT / 32, DIN / 32), 256>>>(W_q, W_k, HDTOT, Ww); // idx 2
    k_proj<<<132, 256, MMA_SMEM>>>(Xn, Xg, Ww, Wy, qb, kb, yq, yk);         // idx 3 (profiled)
    k_f0<<<1, 512>>>(f0);                                                   // idx 4

    k_splitqk<<<SP * HDTOT / 256, 256>>>(qb, kb, Qs, Ks);

    dim3 gs(SP / 32, NH);
    k_suffix<<<gs, 256, SUF_SMEM>>>(qb, qrb, W_pos, b_pos, TQ);
    k_suffix<<<gs, 256, SUF_SMEM>>>(kb, krb, W_pos, b_pos, TK);
    k_fold<<<SP, 128>>>(TQ, TK, W_pair, RQ, RK);

    k_scores<<<dim3(4, 2, NH), 256, MMA_SMEM>>>(Qs, Ks, Sb);

    k_pair2<<<dim3(SP, 4), 256>>>(Sb, RQ, RK, f0, W_pair, b_pair, yq, yk, out);
}